// round 13
// baseline (speedup 1.0000x reference)
#include <cuda_runtime.h>
#include <cuda_fp16.h>
#include <cstdint>

// Problem constants
constexpr int cB = 4;
constexpr int cT = 2048;
constexpr int cC = 1024;
constexpr int cH = 16;
constexpr int cD = 64;
constexpr int cM = cB * cT;          // 8192
constexpr int cNqkv = 3 * cC;        // 3072
constexpr int cNWq = cNqkv * cC;
constexpr int cNWo = cC * cC;
constexpr int cK = 1024;

// -------------------- device scratch --------------------
__device__ float g_partial[1024];
__device__ float g_scale_inv;
__device__ int8_t g_wq8[cNWq];                 // ternary qkv weights (int8, exact)
__device__ int8_t g_wo8[cNWo];                 // ternary out-proj weights
__device__ int8_t g_x0[cM * cK], g_x1[cM * cK], g_x2[cM * cK];   // x int8 planes
__device__ int8_t g_a0[cM * cK], g_a1[cM * cK], g_a2[cM * cK];   // attn-out planes
__device__ float g_q[cB * cH * cT * cD];       // [B,H,T,D]
__device__ float g_k[cB * cH * cT * cD];
__device__ float g_v[cB * cH * cT * cD];
__device__ float g_vt[cB * cH * cD * cT];      // V transposed: [B,H,D,T]

// -------------------- absmean scale --------------------
__global__ void abssum_partial_kernel(const float* __restrict__ w, int n) {
    __shared__ float sd[256];
    int chunk = (n + (int)gridDim.x - 1) / (int)gridDim.x;
    int start = (int)blockIdx.x * chunk;
    int end = start + chunk; if (end > n) end = n;
    float s = 0.f;
    for (int i = start + (int)threadIdx.x; i < end; i += 256) s += fabsf(w[i]);
    sd[threadIdx.x] = s;
    __syncthreads();
    for (int o = 128; o > 0; o >>= 1) {
        if ((int)threadIdx.x < o) sd[threadIdx.x] += sd[threadIdx.x + o];
        __syncthreads();
    }
    if (threadIdx.x == 0) g_partial[blockIdx.x] = sd[0];
}

__global__ void finalize_scale_kernel(float inv_n) {
    __shared__ float sd[256];
    float s = 0.f;
    for (int i = threadIdx.x; i < 1024; i += 256) s += g_partial[i];
    sd[threadIdx.x] = s;
    __syncthreads();
    for (int o = 128; o > 0; o >>= 1) {
        if ((int)threadIdx.x < o) sd[threadIdx.x] += sd[threadIdx.x + o];
        __syncthreads();
    }
    if (threadIdx.x == 0) {
        float sc = fmaxf(sd[0] * inv_n, 1e-8f);
        g_scale_inv = 1.0f / sc;
    }
}

template <int WHICH>
__global__ void quantize_kernel(const float* __restrict__ w, int n4) {
    int i = (int)blockIdx.x * 256 + (int)threadIdx.x;
    if (i >= n4) return;
    float inv = g_scale_inv;
    float4 v = ((const float4*)w)[i];
    char4 q;
    q.x = (char)(int)fminf(1.f, fmaxf(-1.f, rintf(v.x * inv)));
    q.y = (char)(int)fminf(1.f, fmaxf(-1.f, rintf(v.y * inv)));
    q.z = (char)(int)fminf(1.f, fmaxf(-1.f, rintf(v.z * inv)));
    q.w = (char)(int)fminf(1.f, fmaxf(-1.f, rintf(v.w * inv)));
    int8_t* dst = (WHICH == 0) ? g_wq8 : g_wo8;
    ((char4*)dst)[i] = q;
}

// -------------------- helpers --------------------
__device__ __forceinline__ void cp_async16(uint32_t smem_addr, const void* gptr) {
    asm volatile("cp.async.cg.shared.global [%0], [%1], 16;\n" ::"r"(smem_addr), "l"(gptr));
}
__device__ __forceinline__ void cp_commit() { asm volatile("cp.async.commit_group;\n"); }
template <int N>
__device__ __forceinline__ void cp_wait() { asm volatile("cp.async.wait_group %0;\n" ::"n"(N)); }

__device__ __forceinline__ void split2_fp16(float a, __half& h, __half& l) {
    h = __float2half_rn(a);
    l = __float2half_rn(a - __half2float(h));
}
__device__ __forceinline__ void mma_f16(float* d, const uint32_t* a, const uint32_t* b) {
    asm volatile(
        "mma.sync.aligned.m16n8k16.row.col.f32.f16.f16.f32 "
        "{%0,%1,%2,%3}, {%4,%5,%6,%7}, {%8,%9}, {%0,%1,%2,%3};\n"
        : "+f"(d[0]), "+f"(d[1]), "+f"(d[2]), "+f"(d[3])
        : "r"(a[0]), "r"(a[1]), "r"(a[2]), "r"(a[3]), "r"(b[0]), "r"(b[1]));
}
__device__ __forceinline__ void mma_s8(int* d, const uint32_t* a, const uint32_t* b) {
    asm volatile(
        "mma.sync.aligned.m16n8k32.row.col.s32.s8.s8.s32 "
        "{%0,%1,%2,%3}, {%4,%5,%6,%7}, {%8,%9}, {%0,%1,%2,%3};\n"
        : "+r"(d[0]), "+r"(d[1]), "+r"(d[2]), "+r"(d[3])
        : "r"(a[0]), "r"(a[1]), "r"(a[2]), "r"(a[3]), "r"(b[0]), "r"(b[1]));
}
__device__ __forceinline__ void ldsm4(uint32_t addr, uint32_t* r) {
    asm volatile("ldmatrix.sync.aligned.m8n8.x4.shared.b16 {%0,%1,%2,%3}, [%4];\n"
                 : "=r"(r[0]), "=r"(r[1]), "=r"(r[2]), "=r"(r[3]) : "r"(addr));
}

// exact 3-plane int8 split, scales (s0, s1=s0/256, s2=s0/65536)
__device__ __forceinline__ void split3_i8(float a, float inv0, float s0, float inv1,
                                          float s1, float inv2, int& q0, int& q1, int& q2) {
    float p0 = fminf(127.f, fmaxf(-127.f, rintf(a * inv0)));
    float r1 = fmaf(p0, -s0, a);
    float p1 = fminf(127.f, fmaxf(-127.f, rintf(r1 * inv1)));
    float r2 = fmaf(p1, -s1, r1);
    float p2 = fminf(127.f, fmaxf(-127.f, rintf(r2 * inv2)));
    q0 = (int)p0; q1 = (int)p1; q2 = (int)p2;
}

// x scales: s0=2^-4, s1=2^-12, s2=2^-20
constexpr float XS0 = 0.0625f, XS1 = 0.000244140625f, XS2 = 9.5367431640625e-7f;
constexpr float XI0 = 16.f, XI1 = 4096.f, XI2 = 1048576.f;
// o scales: s0=2, s1=2^-7, s2=2^-15
constexpr float OS0 = 2.f, OS1 = 0.0078125f, OS2 = 3.0517578125e-5f;
constexpr float OI0 = 0.5f, OI1 = 128.f, OI2 = 32768.f;

// -------------------- split x into 3 int8 planes --------------------
__global__ void split_x_kernel(const float* __restrict__ x) {
    int i = (int)blockIdx.x * 256 + (int)threadIdx.x;     // float4 index
    float4 v = ((const float4*)x)[i];
    int q0[4], q1[4], q2[4];
    split3_i8(v.x, XI0, XS0, XI1, XS1, XI2, q0[0], q1[0], q2[0]);
    split3_i8(v.y, XI0, XS0, XI1, XS1, XI2, q0[1], q1[1], q2[1]);
    split3_i8(v.z, XI0, XS0, XI1, XS1, XI2, q0[2], q1[2], q2[2]);
    split3_i8(v.w, XI0, XS0, XI1, XS1, XI2, q0[3], q1[3], q2[3]);
    ((char4*)g_x0)[i] = make_char4((char)q0[0], (char)q0[1], (char)q0[2], (char)q0[3]);
    ((char4*)g_x1)[i] = make_char4((char)q1[0], (char)q1[1], (char)q1[2], (char)q1[3]);
    ((char4*)g_x2)[i] = make_char4((char)q2[0], (char)q2[1], (char)q2[2], (char)q2[3]);
}

// -------------------- int8 3-plane tensor-core GEMM --------------------
// C[m][n] = sum_k A[m][k]*W[n][k]; A = s0*p0+s1*p1+s2*p2 int8 planes, W ternary int8.
// CTA tile 128x64, 8 warps (16 rows each), mma m16n8k32, int32 exact accum.
// smem rows: 64 int8 (one K-stage) in 80B stride (conflict-free ldsm); 3-deep pipeline.
constexpr int APL8 = 128 * 80;                // A plane bytes per stage (10240)
constexpr int BPL8 = 64 * 80;                 // B bytes per stage (5120)
constexpr int STG8 = 3 * APL8 + BPL8;         // 35840
constexpr int GEMM8_SMEM = 3 * STG8;          // 107520

template <int MODE>
__global__ __launch_bounds__(256) void gemm_i8_kernel(float* __restrict__ Cparam) {
    extern __shared__ char smc[];
    const int8_t* A0 = (MODE == 0) ? g_x0 : g_a0;
    const int8_t* A1 = (MODE == 0) ? g_x1 : g_a1;
    const int8_t* A2 = (MODE == 0) ? g_x2 : g_a2;
    const int8_t* W8 = (MODE == 0) ? g_wq8 : g_wo8;
    const float S0 = (MODE == 0) ? XS0 : OS0;
    const float S1 = (MODE == 0) ? XS1 : OS1;
    const float S2 = (MODE == 0) ? XS2 : OS2;

    const int tid = threadIdx.x;
    const int lane = tid & 31, wid = tid >> 5;
    const int g = lane >> 2, l4 = lane & 3;
    const int m0 = (int)blockIdx.y * 128;
    const int n0 = (int)blockIdx.x * 64;
    const int wm = wid * 16;

    int acc[3][8][4];
#pragma unroll
    for (int p = 0; p < 3; p++)
#pragma unroll
        for (int nt = 0; nt < 8; nt++)
#pragma unroll
            for (int c = 0; c < 4; c++) acc[p][nt][c] = 0;

    const uint32_t sbase = (uint32_t)__cvta_generic_to_shared(smc);

    const int aRow = (lane & 7) + ((lane >> 3) & 1) * 8;
    const int aColB = ((lane >> 4) & 1) * 16;
    const int bRow = (lane & 7) + ((lane >> 4) & 1) * 8;
    const int bColB = ((lane >> 3) & 1) * 16;

    auto load_stage = [&](int s) {
        uint32_t stg = sbase + (uint32_t)((s % 3) * STG8);
        int k0 = s * 64;
#pragma unroll
        for (int i = 0; i < 7; i++) {
            int id = tid + i * 256;               // 0..1791
            if (id < 1536) {                      // A planes: 3 x 512 chunks
                int p = id >> 9, rem = id & 511;
                int r = rem >> 2, c = rem & 3;
                const int8_t* src = (p == 0) ? A0 : (p == 1) ? A1 : A2;
                cp_async16(stg + p * APL8 + r * 80 + c * 16,
                           src + (size_t)(m0 + r) * cK + k0 + c * 16);
            } else {                              // B: 256 chunks
                int id2 = id - 1536;
                int r = id2 >> 2, c = id2 & 3;
                cp_async16(stg + 3 * APL8 + r * 80 + c * 16,
                           W8 + (size_t)(n0 + r) * cK + k0 + c * 16);
            }
        }
        cp_commit();
    };

    const int NS = cK / 64;   // 16
    load_stage(0);
    load_stage(1);

    for (int s = 0; s < NS; s++) {
        if (s + 2 < NS) load_stage(s + 2);
        else cp_commit();                          // keep group count uniform
        cp_wait<2>();
        __syncthreads();

        uint32_t stg = sbase + (uint32_t)((s % 3) * STG8);
        uint32_t bStg = stg + 3 * APL8;
#pragma unroll
        for (int ks = 0; ks < 2; ks++) {
            const int kB = ks * 32;               // 32 int8 per k-step = 32 B
            uint32_t af[3][4];
#pragma unroll
            for (int p = 0; p < 3; p++)
                ldsm4(stg + p * APL8 + (wm + aRow) * 80 + kB + aColB, af[p]);
            uint32_t bf[8][2];
#pragma unroll
            for (int np = 0; np < 4; np++) {
                uint32_t t4[4];
                ldsm4(bStg + (np * 16 + bRow) * 80 + kB + bColB, t4);
                bf[2 * np][0] = t4[0]; bf[2 * np][1] = t4[1];
                bf[2 * np + 1][0] = t4[2]; bf[2 * np + 1][1] = t4[3];
            }
#pragma unroll
            for (int p = 0; p < 3; p++)
#pragma unroll
                for (int nt = 0; nt < 8; nt++) mma_s8(acc[p][nt], af[p], bf[nt]);
        }
        __syncthreads();
    }

    // epilogue: rows (g, g+8); cols l4*2,+1 per 8-col n-tile; combine planes in fp32
#pragma unroll
    for (int h8 = 0; h8 < 2; h8++) {
        int m = m0 + wm + g + h8 * 8;
#pragma unroll
        for (int nt = 0; nt < 8; nt++) {
            int n = n0 + nt * 8 + l4 * 2;
            float v0 = fmaf(S0, (float)acc[0][nt][h8 * 2 + 0],
                       fmaf(S1, (float)acc[1][nt][h8 * 2 + 0],
                            S2 * (float)acc[2][nt][h8 * 2 + 0]));
            float v1 = fmaf(S0, (float)acc[0][nt][h8 * 2 + 1],
                       fmaf(S1, (float)acc[1][nt][h8 * 2 + 1],
                            S2 * (float)acc[2][nt][h8 * 2 + 1]));
            float2 val = make_float2(v0, v1);
            if (MODE == 0) {
                int b = m >> 11;
                int t = m & 2047;
                int part = n >> 10;
                int c = n & 1023;
                int hh = c >> 6;
                int d = c & 63;
                float* dst = (part == 0) ? g_q : (part == 1) ? g_k : g_v;
                *(float2*)&dst[((size_t)(b * cH + hh) * cT + t) * cD + d] = val;
            } else {
                *(float2*)&Cparam[(size_t)m * cC + n] = val;
            }
        }
    }
}

// -------------------- V transpose --------------------
__global__ void transpose_v_kernel() {
    __shared__ float tile[32][33];
    int bh = blockIdx.z;
    int t0 = blockIdx.x * 32, d0 = blockIdx.y * 32;
    int tx = threadIdx.x, ty = threadIdx.y;
#pragma unroll
    for (int i = 0; i < 32; i += 8)
        tile[ty + i][tx] = g_v[((size_t)bh * cT + t0 + ty + i) * cD + d0 + tx];
    __syncthreads();
#pragma unroll
    for (int i = 0; i < 32; i += 8)
        g_vt[((size_t)bh * cD + d0 + ty + i) * cT + t0 + tx] = tile[tx][ty + i];
}

// -------------------- fp16 2-plane tensor-core flash attention (causal) --------------------
constexpr int HST = 72;                        // half stride per row (144 B)
constexpr int QPL2 = 128 * HST;
constexpr int KPL2 = 64 * HST;
constexpr int ATTN_SMEM = (2 * QPL2 + 4 * KPL2 + 2 * QPL2) * 2;   // 110592 B

__global__ __launch_bounds__(256) void flash_attn_f16_kernel() {
    extern __shared__ __half smh[];
    __half* QH = smh;
    __half* QL = QH + QPL2;
    __half* KH = QL + QPL2;
    __half* KL = KH + KPL2;
    __half* VH = KL + KPL2;
    __half* VL = VH + KPL2;
    __half* PH = VL + KPL2;
    __half* PL = PH + QPL2;

    const int tid = threadIdx.x;
    const int lane = tid & 31, wid = tid >> 5;
    const int g = lane >> 2, l4 = lane & 3;
    const int bh = blockIdx.y;
    const int qt = (int)gridDim.x - 1 - (int)blockIdx.x;
    const int m0 = wid * 16;

    const uint32_t sbase = (uint32_t)__cvta_generic_to_shared(smh);
    const uint32_t qhB = sbase, qlB = sbase + QPL2 * 2;
    const uint32_t khB = qlB + QPL2 * 2, klB = khB + KPL2 * 2;
    const uint32_t vhB = klB + KPL2 * 2, vlB = vhB + KPL2 * 2;
    const uint32_t phB = vlB + KPL2 * 2, plB = phB + QPL2 * 2;

    const int aRow = (lane & 7) + ((lane >> 3) & 1) * 8;
    const int aColB = ((lane >> 4) & 1) * 16;
    const int bRow = (lane & 7) + ((lane >> 4) & 1) * 8;
    const int bColB = ((lane >> 3) & 1) * 16;

    const float* Qg = g_q + ((size_t)bh * cT + qt * 128) * cD;
#pragma unroll
    for (int it = 0; it < 8; it++) {
        int idx4 = tid + it * 256;
        int row = idx4 >> 4, c4 = idx4 & 15;
        float4 v = ((const float4*)Qg)[idx4];
        __half h0, l0, h1, l1, h2, l2, h3, l3;
        split2_fp16(v.x * 0.125f, h0, l0);
        split2_fp16(v.y * 0.125f, h1, l1);
        split2_fp16(v.z * 0.125f, h2, l2);
        split2_fp16(v.w * 0.125f, h3, l3);
        int base = row * HST + c4 * 4;
        *(__half2*)&QH[base] = __halves2half2(h0, h1);
        *(__half2*)&QH[base + 2] = __halves2half2(h2, h3);
        *(__half2*)&QL[base] = __halves2half2(l0, l1);
        *(__half2*)&QL[base + 2] = __halves2half2(l2, l3);
    }

    float m_i[2] = {-1e30f, -1e30f}, l_i[2] = {0.f, 0.f};
    float O[8][4];
#pragma unroll
    for (int nt = 0; nt < 8; nt++)
#pragma unroll
        for (int c = 0; c < 4; c++) O[nt][c] = 0.f;

    const int ktmax = 2 * qt + 1;
    for (int kt = 0; kt <= ktmax; kt++) {
        __syncthreads();
        const float* Kg = g_k + ((size_t)bh * cT + kt * 64) * cD;
        const float* VTg = g_vt + (size_t)bh * cD * cT + kt * 64;
#pragma unroll
        for (int it = 0; it < 4; it++) {
            int idx4 = tid + it * 256;
            int row = idx4 >> 4, c4 = idx4 & 15;
            int base = row * HST + c4 * 4;
            float4 kv = ((const float4*)Kg)[idx4];
            __half h0, l0, h1, l1, h2, l2, h3, l3;
            split2_fp16(kv.x, h0, l0); split2_fp16(kv.y, h1, l1);
            split2_fp16(kv.z, h2, l2); split2_fp16(kv.w, h3, l3);
            *(__half2*)&KH[base] = __halves2half2(h0, h1);
            *(__half2*)&KH[base + 2] = __halves2half2(h2, h3);
            *(__half2*)&KL[base] = __halves2half2(l0, l1);
            *(__half2*)&KL[base + 2] = __halves2half2(l2, l3);
            float4 vv = *(const float4*)(VTg + (size_t)row * cT + c4 * 4);
            split2_fp16(vv.x, h0, l0); split2_fp16(vv.y, h1, l1);
            split2_fp16(vv.z, h2, l2); split2_fp16(vv.w, h3, l3);
            *(__half2*)&VH[base] = __halves2half2(h0, h1);
            *(__half2*)&VH[base + 2] = __halves2half2(h2, h3);
            *(__half2*)&VL[base] = __halves2half2(l0, l1);
            *(__half2*)&VL[base + 2] = __halves2half2(l2, l3);
        }
        __syncthreads();

        const bool active = (kt * 64 <= qt * 128 + m0 + 15);
        if (active) {
            float s[8][4];
#pragma unroll
            for (int nt = 0; nt < 8; nt++)
#pragma unroll
                for (int c = 0; c < 4; c++) s[nt][c] = 0.f;

#pragma unroll
            for (int kcp = 0; kcp < 4; kcp++) {
                const int kB = kcp * 32;
                uint32_t aH[4], aL[4];
                ldsm4(qhB + 2u * ((m0 + aRow) * HST) + kB + aColB, aH);
                ldsm4(qlB + 2u * ((m0 + aRow) * HST) + kB + aColB, aL);
                uint32_t bfh[8][2], bfl[8][2];
#pragma unroll
                for (int np = 0; np < 4; np++) {
                    uint32_t t4[4];
                    ldsm4(khB + 2u * ((np * 16 + bRow) * HST) + kB + bColB, t4);
                    bfh[2 * np][0] = t4[0]; bfh[2 * np][1] = t4[1];
                    bfh[2 * np + 1][0] = t4[2]; bfh[2 * np + 1][1] = t4[3];
                    ldsm4(klB + 2u * ((np * 16 + bRow) * HST) + kB + bColB, t4);
                    bfl[2 * np][0] = t4[0]; bfl[2 * np][1] = t4[1];
                    bfl[2 * np + 1][0] = t4[2]; bfl[2 * np + 1][1] = t4[3];
                }
#pragma unroll
                for (int nt = 0; nt < 8; nt++) {
                    mma_f16(s[nt], aL, bfh[nt]);
                    mma_f16(s[nt], aH, bfl[nt]);
                    mma_f16(s[nt], aH, bfh[nt]);
                }
            }

            if (kt >= 2 * qt) {
                int q0 = qt * 128 + m0 + g, q1 = q0 + 8;
#pragma unroll
                for (int nt = 0; nt < 8; nt++) {
                    int kc0 = kt * 64 + nt * 8 + 2 * l4;
                    if (kc0 > q0) s[nt][0] = -1e30f;
                    if (kc0 + 1 > q0) s[nt][1] = -1e30f;
                    if (kc0 > q1) s[nt][2] = -1e30f;
                    if (kc0 + 1 > q1) s[nt][3] = -1e30f;
                }
            }

#pragma unroll
            for (int r = 0; r < 2; r++) {
                float rm = -1e30f;
#pragma unroll
                for (int nt = 0; nt < 8; nt++)
                    rm = fmaxf(rm, fmaxf(s[nt][2 * r], s[nt][2 * r + 1]));
                rm = fmaxf(rm, __shfl_xor_sync(0xffffffffu, rm, 1));
                rm = fmaxf(rm, __shfl_xor_sync(0xffffffffu, rm, 2));
                float mnew = fmaxf(m_i[r], rm);
                float alpha = __expf(m_i[r] - mnew);
                float rs = 0.f;
#pragma unroll
                for (int nt = 0; nt < 8; nt++) {
                    s[nt][2 * r] = __expf(s[nt][2 * r] - mnew);
                    s[nt][2 * r + 1] = __expf(s[nt][2 * r + 1] - mnew);
                    rs += s[nt][2 * r] + s[nt][2 * r + 1];
                }
                rs += __shfl_xor_sync(0xffffffffu, rs, 1);
                rs += __shfl_xor_sync(0xffffffffu, rs, 2);
                l_i[r] = l_i[r] * alpha + rs;
                m_i[r] = mnew;
#pragma unroll
                for (int nt = 0; nt < 8; nt++) {
                    O[nt][2 * r] *= alpha;
                    O[nt][2 * r + 1] *= alpha;
                }
            }

#pragma unroll
            for (int nt = 0; nt < 8; nt++) {
                int col = nt * 8 + 2 * l4;
                __half h0, l0, h1, l1;
                split2_fp16(s[nt][0], h0, l0); split2_fp16(s[nt][1], h1, l1);
                *(__half2*)&PH[(m0 + g) * HST + col] = __halves2half2(h0, h1);
                *(__half2*)&PL[(m0 + g) * HST + col] = __halves2half2(l0, l1);
                split2_fp16(s[nt][2], h0, l0); split2_fp16(s[nt][3], h1, l1);
                *(__half2*)&PH[(m0 + g + 8) * HST + col] = __halves2half2(h0, h1);
                *(__half2*)&PL[(m0 + g + 8) * HST + col] = __halves2half2(l0, l1);
            }
            __syncwarp();

#pragma unroll
            for (int kcp = 0; kcp < 4; kcp++) {
                const int kB = kcp * 32;
                uint32_t pH[4], pL[4];
                ldsm4(phB + 2u * ((m0 + aRow) * HST) + kB + aColB, pH);
                ldsm4(plB + 2u * ((m0 + aRow) * HST) + kB + aColB, pL);
#pragma unroll
                for (int np = 0; np < 4; np++) {
                    uint32_t th[4], tl[4];
                    ldsm4(vhB + 2u * ((np * 16 + bRow) * HST) + kB + bColB, th);
                    ldsm4(vlB + 2u * ((np * 16 + bRow) * HST) + kB + bColB, tl);
                    uint32_t vh0[2] = {th[0], th[1]}, vh1[2] = {th[2], th[3]};
                    uint32_t vl0[2] = {tl[0], tl[1]}, vl1[2] = {tl[2], tl[3]};
                    mma_f16(O[2 * np], pL, vh0);
                    mma_f16(O[2 * np], pH, vl0);
                    mma_f16(O[2 * np], pH, vh0);
                    mma_f16(O[2 * np + 1], pL, vh1);
                    mma_f16(O[2 * np + 1], pH, vl1);
                    mma_f16(O[2 * np + 1], pH, vh1);
                }
            }
        }
    }

    // epilogue -> 3 int8 planes for the output projection
    int b = bh >> 4, h = bh & 15;
    float inv0 = 1.0f / l_i[0], inv1 = 1.0f / l_i[1];
    int q0 = qt * 128 + m0 + g;
    size_t row0 = (size_t)(b * cT) + q0;
#pragma unroll
    for (int nt = 0; nt < 8; nt++) {
        int d = h * 64 + nt * 8 + 2 * l4;
        int a0, a1, a2, b0, b1, b2;
        split3_i8(O[nt][0] * inv0, OI0, OS0, OI1, OS1, OI2, a0, a1, a2);
        split3_i8(O[nt][1] * inv0, OI0, OS0, OI1, OS1, OI2, b0, b1, b2);
        *(char2*)&g_a0[row0 * cC + d] = make_char2((char)a0, (char)b0);
        *(char2*)&g_a1[row0 * cC + d] = make_char2((char)a1, (char)b1);
        *(char2*)&g_a2[row0 * cC + d] = make_char2((char)a2, (char)b2);
        split3_i8(O[nt][2] * inv1, OI0, OS0, OI1, OS1, OI2, a0, a1, a2);
        split3_i8(O[nt][3] * inv1, OI0, OS0, OI1, OS1, OI2, b0, b1, b2);
        *(char2*)&g_a0[(row0 + 8) * cC + d] = make_char2((char)a0, (char)b0);
        *(char2*)&g_a1[(row0 + 8) * cC + d] = make_char2((char)a1, (char)b1);
        *(char2*)&g_a2[(row0 + 8) * cC + d] = make_char2((char)a2, (char)b2);
    }
}

// -------------------- launch --------------------
extern "C" void kernel_launch(void* const* d_in, const int* in_sizes, int n_in,
                              void* d_out, int out_size) {
    (void)in_sizes; (void)n_in; (void)out_size;
    const float* x = (const float*)d_in[0];
    const float* w_qkv = (const float*)d_in[1];
    const float* w_out = (const float*)d_in[2];
    float* out = (float*)d_out;

    abssum_partial_kernel<<<1024, 256>>>(w_qkv, cNWq);
    finalize_scale_kernel<<<1, 256>>>(1.0f / (float)cNWq);
    quantize_kernel<0><<<cNWq / 4 / 256, 256>>>(w_qkv, cNWq / 4);
    abssum_partial_kernel<<<1024, 256>>>(w_out, cNWo);
    finalize_scale_kernel<<<1, 256>>>(1.0f / (float)cNWo);
    quantize_kernel<1><<<cNWo / 4 / 256, 256>>>(w_out, cNWo / 4);

    split_x_kernel<<<cM * cK / 4 / 256, 256>>>(x);

    // qkv projection (int8 3-plane, exact int32 accumulation)
    {
        cudaFuncSetAttribute(gemm_i8_kernel<0>,
                             cudaFuncAttributeMaxDynamicSharedMemorySize, GEMM8_SMEM);
        dim3 grid(cNqkv / 64, cM / 128);
        gemm_i8_kernel<0><<<grid, 256, GEMM8_SMEM>>>(nullptr);
    }

    // V transpose
    {
        dim3 grid(cT / 32, cD / 32, cB * cH);
        transpose_v_kernel<<<grid, dim3(32, 8)>>>();
    }

    // fp16 tensor-core causal flash attention
    {
        cudaFuncSetAttribute(flash_attn_f16_kernel,
                             cudaFuncAttributeMaxDynamicSharedMemorySize, ATTN_SMEM);
        dim3 grid(cT / 128, cB * cH);
        flash_attn_f16_kernel<<<grid, 256, ATTN_SMEM>>>();
    }

    // output projection (int8 3-plane)
    {
        cudaFuncSetAttribute(gemm_i8_kernel<1>,
                             cudaFuncAttributeMaxDynamicSharedMemorySize, GEMM8_SMEM);
        dim3 grid(cC / 64, cM / 128);
        gemm_i8_kernel<1><<<grid, 256, GEMM8_SMEM>>>(out);
    }
}

// round 14
// speedup vs baseline: 2.2698x; 2.2698x over previous
#include <cuda_runtime.h>
#include <cuda_fp16.h>
#include <cstdint>

// Problem constants
constexpr int cB = 4;
constexpr int cT = 2048;
constexpr int cC = 1024;
constexpr int cH = 16;
constexpr int cD = 64;
constexpr int cM = cB * cT;          // 8192
constexpr int cNqkv = 3 * cC;        // 3072
constexpr int cNWq = cNqkv * cC;
constexpr int cNWo = cC * cC;
constexpr int cK = 1024;
constexpr int cBHT = cB * cH * cT;   // 131072 rows of width 64

// -------------------- device scratch --------------------
__device__ float g_partial[1024];
__device__ float g_scale_inv;
__device__ __half g_wqh[cNWq];                 // ternary qkv weights (fp16, exact)
__device__ __half g_woh[cNWo];                 // ternary out-proj weights
__device__ __half g_xh[cM * cK], g_xl[cM * cK];   // x planes (fp16 hi/lo)
__device__ __half g_ah[cM * cK], g_al[cM * cK];   // attn-out planes
__device__ __half g_qh[cBHT * cD], g_ql[cBHT * cD];   // Q planes [B,H,T,D], pre-scaled 1/8
__device__ __half g_kh[cBHT * cD], g_kl[cBHT * cD];   // K planes [B,H,T,D]
__device__ __half g_vth[cBHT * cD], g_vtl[cBHT * cD]; // V^T planes [B,H,D,T]
__device__ float g_v[cBHT * cD];               // V fp32 [B,H,T,D] (for transpose)

// -------------------- absmean scale --------------------
__global__ void abssum_partial_kernel(const float* __restrict__ w, int n) {
    __shared__ float sd[256];
    int chunk = (n + (int)gridDim.x - 1) / (int)gridDim.x;
    int start = (int)blockIdx.x * chunk;
    int end = start + chunk; if (end > n) end = n;
    float s = 0.f;
    for (int i = start + (int)threadIdx.x; i < end; i += 256) s += fabsf(w[i]);
    sd[threadIdx.x] = s;
    __syncthreads();
    for (int o = 128; o > 0; o >>= 1) {
        if ((int)threadIdx.x < o) sd[threadIdx.x] += sd[threadIdx.x + o];
        __syncthreads();
    }
    if (threadIdx.x == 0) g_partial[blockIdx.x] = sd[0];
}

__global__ void finalize_scale_kernel(float inv_n) {
    __shared__ float sd[256];
    float s = 0.f;
    for (int i = threadIdx.x; i < 1024; i += 256) s += g_partial[i];
    sd[threadIdx.x] = s;
    __syncthreads();
    for (int o = 128; o > 0; o >>= 1) {
        if ((int)threadIdx.x < o) sd[threadIdx.x] += sd[threadIdx.x + o];
        __syncthreads();
    }
    if (threadIdx.x == 0) {
        float sc = fmaxf(sd[0] * inv_n, 1e-8f);
        g_scale_inv = 1.0f / sc;
    }
}

template <int WHICH>
__global__ void quantize_kernel(const float* __restrict__ w, int n4) {
    int i = (int)blockIdx.x * 256 + (int)threadIdx.x;
    if (i >= n4) return;
    float inv = g_scale_inv;
    float4 v = ((const float4*)w)[i];
    __half* dst = (WHICH == 0) ? g_wqh : g_woh;
    __half2* d2 = (__half2*)(dst + (size_t)i * 4);
    d2[0] = __floats2half2_rn(fminf(1.f, fmaxf(-1.f, rintf(v.x * inv))),
                              fminf(1.f, fmaxf(-1.f, rintf(v.y * inv))));
    d2[1] = __floats2half2_rn(fminf(1.f, fmaxf(-1.f, rintf(v.z * inv))),
                              fminf(1.f, fmaxf(-1.f, rintf(v.w * inv))));
}

// -------------------- helpers --------------------
__device__ __forceinline__ void cp_async16(uint32_t smem_addr, const void* gptr) {
    asm volatile("cp.async.cg.shared.global [%0], [%1], 16;\n" ::"r"(smem_addr), "l"(gptr));
}
__device__ __forceinline__ void cp_commit() { asm volatile("cp.async.commit_group;\n"); }
template <int N>
__device__ __forceinline__ void cp_wait() { asm volatile("cp.async.wait_group %0;\n" ::"n"(N)); }

__device__ __forceinline__ void split2_fp16(float a, __half& h, __half& l) {
    h = __float2half_rn(a);
    l = __float2half_rn(a - __half2float(h));
}
__device__ __forceinline__ void mma_f16(float* d, const uint32_t* a, const uint32_t* b) {
    asm volatile(
        "mma.sync.aligned.m16n8k16.row.col.f32.f16.f16.f32 "
        "{%0,%1,%2,%3}, {%4,%5,%6,%7}, {%8,%9}, {%0,%1,%2,%3};\n"
        : "+f"(d[0]), "+f"(d[1]), "+f"(d[2]), "+f"(d[3])
        : "r"(a[0]), "r"(a[1]), "r"(a[2]), "r"(a[3]), "r"(b[0]), "r"(b[1]));
}
__device__ __forceinline__ void ldsm4(uint32_t addr, uint32_t* r) {
    asm volatile("ldmatrix.sync.aligned.m8n8.x4.shared.b16 {%0,%1,%2,%3}, [%4];\n"
                 : "=r"(r[0]), "=r"(r[1]), "=r"(r[2]), "=r"(r[3]) : "r"(addr));
}

// -------------------- split x into 2 fp16 planes --------------------
__global__ void split_x_kernel(const float* __restrict__ x) {
    int i = (int)blockIdx.x * 256 + (int)threadIdx.x;     // float4 index
    float4 v = ((const float4*)x)[i];
    __half h[4], l[4];
    split2_fp16(v.x, h[0], l[0]);
    split2_fp16(v.y, h[1], l[1]);
    split2_fp16(v.z, h[2], l[2]);
    split2_fp16(v.w, h[3], l[3]);
    size_t o2 = (size_t)i * 2;
    ((__half2*)g_xh)[o2] = __halves2half2(h[0], h[1]);
    ((__half2*)g_xh)[o2 + 1] = __halves2half2(h[2], h[3]);
    ((__half2*)g_xl)[o2] = __halves2half2(l[0], l[1]);
    ((__half2*)g_xl)[o2 + 1] = __halves2half2(l[2], l[3]);
}

// -------------------- fp16 2-plane tensor-core GEMM --------------------
constexpr int APL_B = 128 * 80;               // one plane, bytes
constexpr int STG_B = 2 * APL_B + APL_B;      // 30720
constexpr int GEMM_SMEM_BYTES = 2 * STG_B;    // 61440

template <int MODE>
__global__ __launch_bounds__(256) void gemm_fp16_kernel(float* __restrict__ Cparam) {
    extern __shared__ char smc[];
    const __half* Ah = (MODE == 0) ? g_xh : g_ah;
    const __half* Al = (MODE == 0) ? g_xl : g_al;
    const __half* Wh = (MODE == 0) ? g_wqh : g_woh;

    const int tid = threadIdx.x;
    const int lane = tid & 31, wid = tid >> 5;
    const int warp_m = (wid >> 1) * 32;
    const int warp_n = (wid & 1) * 64;
    const int g = lane >> 2, l4 = lane & 3;

    const int m0 = (int)blockIdx.y * 128;
    const int n0 = (int)blockIdx.x * 128;

    float acc[2][8][4];
#pragma unroll
    for (int mt = 0; mt < 2; mt++)
#pragma unroll
        for (int nt = 0; nt < 8; nt++)
#pragma unroll
            for (int c = 0; c < 4; c++) acc[mt][nt][c] = 0.f;

    const uint32_t sbase = (uint32_t)__cvta_generic_to_shared(smc);

    const int aRow = (lane & 7) + ((lane >> 3) & 1) * 8;
    const int aColB = ((lane >> 4) & 1) * 16;
    const int bRow = (lane & 7) + ((lane >> 4) & 1) * 8;
    const int bColB = ((lane >> 3) & 1) * 16;

    auto load_stage = [&](int s) {
        uint32_t stg = sbase + (uint32_t)((s & 1) * STG_B);
        int k0 = s * 32;
#pragma unroll
        for (int i = 0; i < 6; i++) {
            int id = tid + i * 256;
            if (id < 1024) {
                int p = id >> 9, rem = id & 511;
                int r = rem >> 2, c = rem & 3;
                const __half* src = (p == 0) ? Ah : Al;
                cp_async16(stg + p * APL_B + r * 80 + c * 16,
                           src + (size_t)(m0 + r) * cK + k0 + c * 8);
            } else {
                int id2 = id - 1024;
                int r = id2 >> 2, c = id2 & 3;
                cp_async16(stg + 2 * APL_B + r * 80 + c * 16,
                           Wh + (size_t)(n0 + r) * cK + k0 + c * 8);
            }
        }
        cp_commit();
    };

    const int NS = cK / 32;
    load_stage(0);

    for (int s = 0; s < NS; s++) {
        if (s + 1 < NS) {
            load_stage(s + 1);
            cp_wait<1>();
        } else {
            cp_wait<0>();
        }
        __syncthreads();

        uint32_t stg = sbase + (uint32_t)((s & 1) * STG_B);
        uint32_t bStg = stg + 2 * APL_B;
#pragma unroll
        for (int ks = 0; ks < 2; ks++) {
            const int kB = ks * 32;
            uint32_t af[2][2][4];
#pragma unroll
            for (int mt = 0; mt < 2; mt++)
#pragma unroll
                for (int p = 0; p < 2; p++)
                    ldsm4(stg + p * APL_B + (warp_m + mt * 16 + aRow) * 80 + kB + aColB,
                          af[mt][p]);
            uint32_t bf[8][2];
#pragma unroll
            for (int np = 0; np < 4; np++) {
                uint32_t t4[4];
                ldsm4(bStg + (warp_n + np * 16 + bRow) * 80 + kB + bColB, t4);
                bf[2 * np][0] = t4[0]; bf[2 * np][1] = t4[1];
                bf[2 * np + 1][0] = t4[2]; bf[2 * np + 1][1] = t4[3];
            }
#pragma unroll
            for (int mt = 0; mt < 2; mt++)
#pragma unroll
                for (int nt = 0; nt < 8; nt++) {
                    mma_f16(acc[mt][nt], af[mt][1], bf[nt]);
                    mma_f16(acc[mt][nt], af[mt][0], bf[nt]);
                }
        }
        __syncthreads();
    }

#pragma unroll
    for (int mt = 0; mt < 2; mt++) {
#pragma unroll
        for (int h8 = 0; h8 < 2; h8++) {
            int m = m0 + warp_m + mt * 16 + g + h8 * 8;
#pragma unroll
            for (int nt = 0; nt < 8; nt++) {
                int n = n0 + warp_n + nt * 8 + l4 * 2;
                float2 val = make_float2(acc[mt][nt][h8 * 2 + 0], acc[mt][nt][h8 * 2 + 1]);
                if (MODE == 0) {
                    int b = m >> 11;
                    int t = m & 2047;
                    int part = n >> 10;
                    int c = n & 1023;
                    int hh = c >> 6;
                    int d = c & 63;
                    size_t off = ((size_t)(b * cH + hh) * cT + t) * cD + d;
                    if (part == 0) {            // Q -> fp16 planes, pre-scaled 1/8
                        __half h0, l0, h1, l1;
                        split2_fp16(val.x * 0.125f, h0, l0);
                        split2_fp16(val.y * 0.125f, h1, l1);
                        *(__half2*)&g_qh[off] = __halves2half2(h0, h1);
                        *(__half2*)&g_ql[off] = __halves2half2(l0, l1);
                    } else if (part == 1) {     // K -> fp16 planes
                        __half h0, l0, h1, l1;
                        split2_fp16(val.x, h0, l0);
                        split2_fp16(val.y, h1, l1);
                        *(__half2*)&g_kh[off] = __halves2half2(h0, h1);
                        *(__half2*)&g_kl[off] = __halves2half2(l0, l1);
                    } else {                    // V -> fp32 (transposed next)
                        *(float2*)&g_v[off] = val;
                    }
                } else {
                    *(float2*)&Cparam[(size_t)m * cC + n] = val;
                }
            }
        }
    }
}

// -------------------- V transpose + split: g_v [bh][T][D] -> planes [bh][D][T] --------------
__global__ void transpose_v_kernel() {
    __shared__ float tile[32][33];
    int bh = blockIdx.z;
    int t0 = blockIdx.x * 32, d0 = blockIdx.y * 32;
    int tx = threadIdx.x, ty = threadIdx.y;
#pragma unroll
    for (int i = 0; i < 32; i += 8)
        tile[ty + i][tx] = g_v[((size_t)bh * cT + t0 + ty + i) * cD + d0 + tx];
    __syncthreads();
#pragma unroll
    for (int i = 0; i < 32; i += 8) {
        float v = tile[tx][ty + i];
        __half h, l;
        split2_fp16(v, h, l);
        size_t off = ((size_t)bh * cD + d0 + ty + i) * cT + t0 + tx;
        g_vth[off] = h;
        g_vtl[off] = l;
    }
}

// -------------------- fp16 2-plane flash attention, cp.async double-buffered ------------
// CTA: 128 q-rows, 8 warps x 16 rows; K-tile 64. All operands pre-split fp16 planes in gmem.
constexpr int HST = 72;                        // half stride per row (144 B)
constexpr int QPL2 = 128 * HST;                // halves per Q plane
constexpr int KPL2 = 64 * HST;                 // halves per K/V plane
constexpr int KVBUF = 4 * KPL2;                // halves per KV buffer (4 planes)
constexpr int ATTN_SMEM = (2 * QPL2 + 2 * KVBUF + 2 * QPL2) * 2;   // 147456 B

__global__ __launch_bounds__(256) void flash_attn_f16_kernel() {
    extern __shared__ __half smh[];

    const int tid = threadIdx.x;
    const int lane = tid & 31, wid = tid >> 5;
    const int g = lane >> 2, l4 = lane & 3;
    const int bh = blockIdx.y;
    const int qt = (int)gridDim.x - 1 - (int)blockIdx.x;   // big tiles first
    const int m0 = wid * 16;

    const uint32_t sbase = (uint32_t)__cvta_generic_to_shared(smh);
    const uint32_t qhB = sbase, qlB = sbase + QPL2 * 2;
    const uint32_t kv0B = qlB + QPL2 * 2;                  // buffer 0 base
    const uint32_t phB = kv0B + 2 * KVBUF * 2, plB = phB + QPL2 * 2;
    __half* PH = smh + 2 * QPL2 + 2 * KVBUF;
    __half* PL = PH + QPL2;

    const int aRow = (lane & 7) + ((lane >> 3) & 1) * 8;
    const int aColB = ((lane >> 4) & 1) * 16;
    const int bRow = (lane & 7) + ((lane >> 4) & 1) * 8;
    const int bColB = ((lane >> 3) & 1) * 16;

    // KV stage loader: 4 planes x 64 rows x 8 chunks = 2048 chunks, 8/thread
    auto load_kv = [&](int kt, int buf) {
        uint32_t dst0 = kv0B + (uint32_t)(buf * KVBUF * 2);
        const __half* kp_h = g_kh + ((size_t)bh * cT + kt * 64) * cD;
        const __half* kp_l = g_kl + ((size_t)bh * cT + kt * 64) * cD;
        const __half* vp_h = g_vth + (size_t)bh * cD * cT + kt * 64;
        const __half* vp_l = g_vtl + (size_t)bh * cD * cT + kt * 64;
#pragma unroll
        for (int i = 0; i < 8; i++) {
            int id = tid + i * 256;               // 0..2047
            int p = id >> 9, rem = id & 511;
            int r = rem >> 3, c = rem & 7;
            uint32_t dst = dst0 + (uint32_t)(p * KPL2 * 2 + r * 144 + c * 16);
            const __half* gp;
            if (p == 0) gp = kp_h + (size_t)r * cD + c * 8;
            else if (p == 1) gp = kp_l + (size_t)r * cD + c * 8;
            else if (p == 2) gp = vp_h + (size_t)r * cT + c * 8;
            else gp = vp_l + (size_t)r * cT + c * 8;
            cp_async16(dst, gp);
        }
        cp_commit();
    };

    // prologue: Q planes (2048 chunks) + KV stage 0, one commit group
    {
        const __half* qp_h = g_qh + ((size_t)bh * cT + qt * 128) * cD;
        const __half* qp_l = g_ql + ((size_t)bh * cT + qt * 128) * cD;
#pragma unroll
        for (int i = 0; i < 8; i++) {
            int id = tid + i * 256;               // 0..2047
            int p = id >> 10, rem = id & 1023;
            int r = rem >> 3, c = rem & 7;
            uint32_t dst = (p == 0 ? qhB : qlB) + (uint32_t)(r * 144 + c * 16);
            const __half* gp = (p == 0 ? qp_h : qp_l) + (size_t)r * cD + c * 8;
            cp_async16(dst, gp);
        }
    }
    load_kv(0, 0);   // commits Q + KV0 together

    float m_i[2] = {-1e30f, -1e30f}, l_i[2] = {0.f, 0.f};
    float O[8][4];
#pragma unroll
    for (int nt = 0; nt < 8; nt++)
#pragma unroll
        for (int c = 0; c < 4; c++) O[nt][c] = 0.f;

    const int ktmax = 2 * qt + 1;
    for (int kt = 0; kt <= ktmax; kt++) {
        if (kt + 1 <= ktmax) {
            load_kv(kt + 1, (kt + 1) & 1);
            cp_wait<1>();
        } else {
            cp_wait<0>();
        }
        __syncthreads();

        const uint32_t kvB = kv0B + (uint32_t)((kt & 1) * KVBUF * 2);
        const uint32_t khB = kvB, klB = kvB + KPL2 * 2;
        const uint32_t vhB = kvB + 2 * KPL2 * 2, vlB = kvB + 3 * KPL2 * 2;

        const bool active = (kt * 64 <= qt * 128 + m0 + 15);
        if (active) {
            // ---- S = Q K^T (3-MMA fp16 2-plane) ----
            float s[8][4];
#pragma unroll
            for (int nt = 0; nt < 8; nt++)
#pragma unroll
                for (int c = 0; c < 4; c++) s[nt][c] = 0.f;

#pragma unroll
            for (int kcp = 0; kcp < 4; kcp++) {
                const int kB = kcp * 32;
                uint32_t aH[4], aL[4];
                ldsm4(qhB + 2u * ((m0 + aRow) * HST) + kB + aColB, aH);
                ldsm4(qlB + 2u * ((m0 + aRow) * HST) + kB + aColB, aL);
                uint32_t bfh[8][2], bfl[8][2];
#pragma unroll
                for (int np = 0; np < 4; np++) {
                    uint32_t t4[4];
                    ldsm4(khB + 2u * ((np * 16 + bRow) * HST) + kB + bColB, t4);
                    bfh[2 * np][0] = t4[0]; bfh[2 * np][1] = t4[1];
                    bfh[2 * np + 1][0] = t4[2]; bfh[2 * np + 1][1] = t4[3];
                    ldsm4(klB + 2u * ((np * 16 + bRow) * HST) + kB + bColB, t4);
                    bfl[2 * np][0] = t4[0]; bfl[2 * np][1] = t4[1];
                    bfl[2 * np + 1][0] = t4[2]; bfl[2 * np + 1][1] = t4[3];
                }
#pragma unroll
                for (int nt = 0; nt < 8; nt++) {
                    mma_f16(s[nt], aL, bfh[nt]);      // Ql.Kh
                    mma_f16(s[nt], aH, bfl[nt]);      // Qh.Kl
                    mma_f16(s[nt], aH, bfh[nt]);      // Qh.Kh
                }
            }

            // ---- causal mask ----
            if (kt >= 2 * qt) {
                int q0 = qt * 128 + m0 + g, q1 = q0 + 8;
#pragma unroll
                for (int nt = 0; nt < 8; nt++) {
                    int kc0 = kt * 64 + nt * 8 + 2 * l4;
                    if (kc0 > q0) s[nt][0] = -1e30f;
                    if (kc0 + 1 > q0) s[nt][1] = -1e30f;
                    if (kc0 > q1) s[nt][2] = -1e30f;
                    if (kc0 + 1 > q1) s[nt][3] = -1e30f;
                }
            }

            // ---- online softmax ----
#pragma unroll
            for (int r = 0; r < 2; r++) {
                float rm = -1e30f;
#pragma unroll
                for (int nt = 0; nt < 8; nt++)
                    rm = fmaxf(rm, fmaxf(s[nt][2 * r], s[nt][2 * r + 1]));
                rm = fmaxf(rm, __shfl_xor_sync(0xffffffffu, rm, 1));
                rm = fmaxf(rm, __shfl_xor_sync(0xffffffffu, rm, 2));
                float mnew = fmaxf(m_i[r], rm);
                float alpha = __expf(m_i[r] - mnew);
                float rs = 0.f;
#pragma unroll
                for (int nt = 0; nt < 8; nt++) {
                    s[nt][2 * r] = __expf(s[nt][2 * r] - mnew);
                    s[nt][2 * r + 1] = __expf(s[nt][2 * r + 1] - mnew);
                    rs += s[nt][2 * r] + s[nt][2 * r + 1];
                }
                rs += __shfl_xor_sync(0xffffffffu, rs, 1);
                rs += __shfl_xor_sync(0xffffffffu, rs, 2);
                l_i[r] = l_i[r] * alpha + rs;
                m_i[r] = mnew;
#pragma unroll
                for (int nt = 0; nt < 8; nt++) {
                    O[nt][2 * r] *= alpha;
                    O[nt][2 * r + 1] *= alpha;
                }
            }

            // ---- stage P (fp16 hi/lo) ----
#pragma unroll
            for (int nt = 0; nt < 8; nt++) {
                int col = nt * 8 + 2 * l4;
                __half h0, l0, h1, l1;
                split2_fp16(s[nt][0], h0, l0); split2_fp16(s[nt][1], h1, l1);
                *(__half2*)&PH[(m0 + g) * HST + col] = __halves2half2(h0, h1);
                *(__half2*)&PL[(m0 + g) * HST + col] = __halves2half2(l0, l1);
                split2_fp16(s[nt][2], h0, l0); split2_fp16(s[nt][3], h1, l1);
                *(__half2*)&PH[(m0 + g + 8) * HST + col] = __halves2half2(h0, h1);
                *(__half2*)&PL[(m0 + g + 8) * HST + col] = __halves2half2(l0, l1);
            }
            __syncwarp();   // P rows are warp-private

            // ---- O += P V ----
#pragma unroll
            for (int kcp = 0; kcp < 4; kcp++) {
                const int kB = kcp * 32;
                uint32_t pH[4], pL[4];
                ldsm4(phB + 2u * ((m0 + aRow) * HST) + kB + aColB, pH);
                ldsm4(plB + 2u * ((m0 + aRow) * HST) + kB + aColB, pL);
#pragma unroll
                for (int np = 0; np < 4; np++) {
                    uint32_t th[4], tl[4];
                    ldsm4(vhB + 2u * ((np * 16 + bRow) * HST) + kB + bColB, th);
                    ldsm4(vlB + 2u * ((np * 16 + bRow) * HST) + kB + bColB, tl);
                    uint32_t vh0[2] = {th[0], th[1]}, vh1[2] = {th[2], th[3]};
                    uint32_t vl0[2] = {tl[0], tl[1]}, vl1[2] = {tl[2], tl[3]};
                    mma_f16(O[2 * np], pL, vh0);          // Pl.Vh
                    mma_f16(O[2 * np], pH, vl0);          // Ph.Vl
                    mma_f16(O[2 * np], pH, vh0);          // Ph.Vh
                    mma_f16(O[2 * np + 1], pL, vh1);
                    mma_f16(O[2 * np + 1], pH, vl1);
                    mma_f16(O[2 * np + 1], pH, vh1);
                }
            }
        }
        __syncthreads();   // all reads of this KV buffer done before it is re-filled
    }

    // ---- epilogue -> 2 fp16 planes for the output projection ----
    int b = bh >> 4, h = bh & 15;
    float inv0 = 1.0f / l_i[0], inv1 = 1.0f / l_i[1];
    int q0 = qt * 128 + m0 + g;
    size_t row0 = (size_t)(b * cT) + q0;
#pragma unroll
    for (int nt = 0; nt < 8; nt++) {
        int d = h * 64 + nt * 8 + 2 * l4;
        __half h0, l0, h1, l1;
        split2_fp16(O[nt][0] * inv0, h0, l0);
        split2_fp16(O[nt][1] * inv0, h1, l1);
        *(__half2*)&g_ah[row0 * cC + d] = __halves2half2(h0, h1);
        *(__half2*)&g_al[row0 * cC + d] = __halves2half2(l0, l1);
        split2_fp16(O[nt][2] * inv1, h0, l0);
        split2_fp16(O[nt][3] * inv1, h1, l1);
        *(__half2*)&g_ah[(row0 + 8) * cC + d] = __halves2half2(h0, h1);
        *(__half2*)&g_al[(row0 + 8) * cC + d] = __halves2half2(l0, l1);
    }
}

// -------------------- launch --------------------
extern "C" void kernel_launch(void* const* d_in, const int* in_sizes, int n_in,
                              void* d_out, int out_size) {
    (void)in_sizes; (void)n_in; (void)out_size;
    const float* x = (const float*)d_in[0];
    const float* w_qkv = (const float*)d_in[1];
    const float* w_out = (const float*)d_in[2];
    float* out = (float*)d_out;

    abssum_partial_kernel<<<1024, 256>>>(w_qkv, cNWq);
    finalize_scale_kernel<<<1, 256>>>(1.0f / (float)cNWq);
    quantize_kernel<0><<<cNWq / 4 / 256, 256>>>(w_qkv, cNWq / 4);
    abssum_partial_kernel<<<1024, 256>>>(w_out, cNWo);
    finalize_scale_kernel<<<1, 256>>>(1.0f / (float)cNWo);
    quantize_kernel<1><<<cNWo / 4 / 256, 256>>>(w_out, cNWo / 4);

    split_x_kernel<<<cM * cK / 4 / 256, 256>>>(x);

    // qkv projection (fp16 2-plane; writes Q/K planes + V fp32)
    {
        cudaFuncSetAttribute(gemm_fp16_kernel<0>,
                             cudaFuncAttributeMaxDynamicSharedMemorySize, GEMM_SMEM_BYTES);
        dim3 grid(cNqkv / 128, cM / 128);
        gemm_fp16_kernel<0><<<grid, 256, GEMM_SMEM_BYTES>>>(nullptr);
    }

    // V transpose + split into planes
    {
        dim3 grid(cT / 32, cD / 32, cB * cH);
        transpose_v_kernel<<<grid, dim3(32, 8)>>>();
    }

    // fp16 tensor-core causal flash attention (cp.async double-buffered)
    {
        cudaFuncSetAttribute(flash_attn_f16_kernel,
                             cudaFuncAttributeMaxDynamicSharedMemorySize, ATTN_SMEM);
        dim3 grid(cT / 128, cB * cH);
        flash_attn_f16_kernel<<<grid, 256, ATTN_SMEM>>>();
    }

    // output projection (fp16 2-plane)
    {
        cudaFuncSetAttribute(gemm_fp16_kernel<1>,
                             cudaFuncAttributeMaxDynamicSharedMemorySize, GEMM_SMEM_BYTES);
        dim3 grid(cC / 128, cM / 128);
        gemm_fp16_kernel<1><<<grid, 256, GEMM_SMEM_BYTES>>>(out);
    }
}

// round 15
// speedup vs baseline: 2.5501x; 1.1235x over previous
#include <cuda_runtime.h>
#include <cuda_fp16.h>
#include <cstdint>

// Problem constants
constexpr int cB = 4;
constexpr int cT = 2048;
constexpr int cC = 1024;
constexpr int cH = 16;
constexpr int cD = 64;
constexpr int cM = cB * cT;          // 8192
constexpr int cNqkv = 3 * cC;        // 3072
constexpr int cNWq = cNqkv * cC;
constexpr int cNWo = cC * cC;
constexpr int cK = 1024;
constexpr int cBHT = cB * cH * cT;   // 131072 rows of width 64

// -------------------- device scratch --------------------
__device__ float g_partial[1024];
__device__ float g_scale_inv;
__device__ __half g_wqh[cNWq];                 // ternary qkv weights (fp16, exact)
__device__ __half g_woh[cNWo];                 // ternary out-proj weights
__device__ __half g_xh[cM * cK], g_xl[cM * cK];   // x planes (fp16 hi/lo)
__device__ __half g_ah[cM * cK];               // attn-out plane (single, fp16)
__device__ __half g_qh[cBHT * cD], g_ql[cBHT * cD];   // Q planes [B,H,T,D], pre-scaled 1/8
__device__ __half g_kh[cBHT * cD], g_kl[cBHT * cD];   // K planes [B,H,T,D]
__device__ __half g_vth[cBHT * cD];            // V^T single plane [B,H,D,T]
__device__ float g_v[cBHT * cD];               // V fp32 [B,H,T,D] (for transpose)

// -------------------- absmean scale --------------------
__global__ void abssum_partial_kernel(const float* __restrict__ w, int n) {
    __shared__ float sd[256];
    int chunk = (n + (int)gridDim.x - 1) / (int)gridDim.x;
    int start = (int)blockIdx.x * chunk;
    int end = start + chunk; if (end > n) end = n;
    float s = 0.f;
    for (int i = start + (int)threadIdx.x; i < end; i += 256) s += fabsf(w[i]);
    sd[threadIdx.x] = s;
    __syncthreads();
    for (int o = 128; o > 0; o >>= 1) {
        if ((int)threadIdx.x < o) sd[threadIdx.x] += sd[threadIdx.x + o];
        __syncthreads();
    }
    if (threadIdx.x == 0) g_partial[blockIdx.x] = sd[0];
}

__global__ void finalize_scale_kernel(float inv_n) {
    __shared__ float sd[256];
    float s = 0.f;
    for (int i = threadIdx.x; i < 1024; i += 256) s += g_partial[i];
    sd[threadIdx.x] = s;
    __syncthreads();
    for (int o = 128; o > 0; o >>= 1) {
        if ((int)threadIdx.x < o) sd[threadIdx.x] += sd[threadIdx.x + o];
        __syncthreads();
    }
    if (threadIdx.x == 0) {
        float sc = fmaxf(sd[0] * inv_n, 1e-8f);
        g_scale_inv = 1.0f / sc;
    }
}

template <int WHICH>
__global__ void quantize_kernel(const float* __restrict__ w, int n4) {
    int i = (int)blockIdx.x * 256 + (int)threadIdx.x;
    if (i >= n4) return;
    float inv = g_scale_inv;
    float4 v = ((const float4*)w)[i];
    __half* dst = (WHICH == 0) ? g_wqh : g_woh;
    __half2* d2 = (__half2*)(dst + (size_t)i * 4);
    d2[0] = __floats2half2_rn(fminf(1.f, fmaxf(-1.f, rintf(v.x * inv))),
                              fminf(1.f, fmaxf(-1.f, rintf(v.y * inv))));
    d2[1] = __floats2half2_rn(fminf(1.f, fmaxf(-1.f, rintf(v.z * inv))),
                              fminf(1.f, fmaxf(-1.f, rintf(v.w * inv))));
}

// -------------------- helpers --------------------
__device__ __forceinline__ void cp_async16(uint32_t smem_addr, const void* gptr) {
    asm volatile("cp.async.cg.shared.global [%0], [%1], 16;\n" ::"r"(smem_addr), "l"(gptr));
}
__device__ __forceinline__ void cp_commit() { asm volatile("cp.async.commit_group;\n"); }
template <int N>
__device__ __forceinline__ void cp_wait() { asm volatile("cp.async.wait_group %0;\n" ::"n"(N)); }

__device__ __forceinline__ void split2_fp16(float a, __half& h, __half& l) {
    h = __float2half_rn(a);
    l = __float2half_rn(a - __half2float(h));
}
__device__ __forceinline__ void mma_f16(float* d, const uint32_t* a, const uint32_t* b) {
    asm volatile(
        "mma.sync.aligned.m16n8k16.row.col.f32.f16.f16.f32 "
        "{%0,%1,%2,%3}, {%4,%5,%6,%7}, {%8,%9}, {%0,%1,%2,%3};\n"
        : "+f"(d[0]), "+f"(d[1]), "+f"(d[2]), "+f"(d[3])
        : "r"(a[0]), "r"(a[1]), "r"(a[2]), "r"(a[3]), "r"(b[0]), "r"(b[1]));
}
__device__ __forceinline__ void ldsm4(uint32_t addr, uint32_t* r) {
    asm volatile("ldmatrix.sync.aligned.m8n8.x4.shared.b16 {%0,%1,%2,%3}, [%4];\n"
                 : "=r"(r[0]), "=r"(r[1]), "=r"(r[2]), "=r"(r[3]) : "r"(addr));
}

// -------------------- split x into 2 fp16 planes --------------------
__global__ void split_x_kernel(const float* __restrict__ x) {
    int i = (int)blockIdx.x * 256 + (int)threadIdx.x;     // float4 index
    float4 v = ((const float4*)x)[i];
    __half h[4], l[4];
    split2_fp16(v.x, h[0], l[0]);
    split2_fp16(v.y, h[1], l[1]);
    split2_fp16(v.z, h[2], l[2]);
    split2_fp16(v.w, h[3], l[3]);
    size_t o2 = (size_t)i * 2;
    ((__half2*)g_xh)[o2] = __halves2half2(h[0], h[1]);
    ((__half2*)g_xh)[o2 + 1] = __halves2half2(h[2], h[3]);
    ((__half2*)g_xl)[o2] = __halves2half2(l[0], l[1]);
    ((__half2*)g_xl)[o2 + 1] = __halves2half2(l[2], l[3]);
}

// -------------------- fp16 tensor-core GEMM (NPL A-planes) --------------------
constexpr int APL_B = 128 * 80;               // one plane, bytes

template <int MODE, int NPL>
__global__ __launch_bounds__(256) void gemm_fp16_kernel(float* __restrict__ Cparam) {
    constexpr int STG = (NPL + 1) * APL_B;     // A planes + B plane per stage
    extern __shared__ char smc[];
    const __half* Ah = (MODE == 0) ? g_xh : g_ah;
    const __half* Al = (MODE == 0) ? g_xl : g_ah;   // unused when NPL==1
    const __half* Wh = (MODE == 0) ? g_wqh : g_woh;

    const int tid = threadIdx.x;
    const int lane = tid & 31, wid = tid >> 5;
    const int warp_m = (wid >> 1) * 32;
    const int warp_n = (wid & 1) * 64;
    const int g = lane >> 2, l4 = lane & 3;

    const int m0 = (int)blockIdx.y * 128;
    const int n0 = (int)blockIdx.x * 128;

    float acc[2][8][4];
#pragma unroll
    for (int mt = 0; mt < 2; mt++)
#pragma unroll
        for (int nt = 0; nt < 8; nt++)
#pragma unroll
            for (int c = 0; c < 4; c++) acc[mt][nt][c] = 0.f;

    const uint32_t sbase = (uint32_t)__cvta_generic_to_shared(smc);

    const int aRow = (lane & 7) + ((lane >> 3) & 1) * 8;
    const int aColB = ((lane >> 4) & 1) * 16;
    const int bRow = (lane & 7) + ((lane >> 4) & 1) * 8;
    const int bColB = ((lane >> 3) & 1) * 16;

    auto load_stage = [&](int s) {
        uint32_t stg = sbase + (uint32_t)((s & 1) * STG);
        int k0 = s * 32;
#pragma unroll
        for (int i = 0; i < 2 * (NPL + 1); i++) {
            int id = tid + i * 256;                   // 0..512*(NPL+1)-1
            if (id < NPL * 512) {
                int p = id >> 9, rem = id & 511;
                int r = rem >> 2, c = rem & 3;
                const __half* src = (p == 0) ? Ah : Al;
                cp_async16(stg + p * APL_B + r * 80 + c * 16,
                           src + (size_t)(m0 + r) * cK + k0 + c * 8);
            } else {
                int id2 = id - NPL * 512;
                int r = id2 >> 2, c = id2 & 3;
                cp_async16(stg + NPL * APL_B + r * 80 + c * 16,
                           Wh + (size_t)(n0 + r) * cK + k0 + c * 8);
            }
        }
        cp_commit();
    };

    const int NS = cK / 32;
    load_stage(0);

    for (int s = 0; s < NS; s++) {
        if (s + 1 < NS) {
            load_stage(s + 1);
            cp_wait<1>();
        } else {
            cp_wait<0>();
        }
        __syncthreads();

        uint32_t stg = sbase + (uint32_t)((s & 1) * STG);
        uint32_t bStg = stg + NPL * APL_B;
#pragma unroll
        for (int ks = 0; ks < 2; ks++) {
            const int kB = ks * 32;
            uint32_t af[2][NPL][4];
#pragma unroll
            for (int mt = 0; mt < 2; mt++)
#pragma unroll
                for (int p = 0; p < NPL; p++)
                    ldsm4(stg + p * APL_B + (warp_m + mt * 16 + aRow) * 80 + kB + aColB,
                          af[mt][p]);
            uint32_t bf[8][2];
#pragma unroll
            for (int np = 0; np < 4; np++) {
                uint32_t t4[4];
                ldsm4(bStg + (warp_n + np * 16 + bRow) * 80 + kB + bColB, t4);
                bf[2 * np][0] = t4[0]; bf[2 * np][1] = t4[1];
                bf[2 * np + 1][0] = t4[2]; bf[2 * np + 1][1] = t4[3];
            }
#pragma unroll
            for (int mt = 0; mt < 2; mt++)
#pragma unroll
                for (int nt = 0; nt < 8; nt++) {
                    if (NPL == 2) mma_f16(acc[mt][nt], af[mt][NPL - 1], bf[nt]);
                    mma_f16(acc[mt][nt], af[mt][0], bf[nt]);
                }
        }
        __syncthreads();
    }

#pragma unroll
    for (int mt = 0; mt < 2; mt++) {
#pragma unroll
        for (int h8 = 0; h8 < 2; h8++) {
            int m = m0 + warp_m + mt * 16 + g + h8 * 8;
#pragma unroll
            for (int nt = 0; nt < 8; nt++) {
                int n = n0 + warp_n + nt * 8 + l4 * 2;
                float2 val = make_float2(acc[mt][nt][h8 * 2 + 0], acc[mt][nt][h8 * 2 + 1]);
                if (MODE == 0) {
                    int b = m >> 11;
                    int t = m & 2047;
                    int part = n >> 10;
                    int c = n & 1023;
                    int hh = c >> 6;
                    int d = c & 63;
                    size_t off = ((size_t)(b * cH + hh) * cT + t) * cD + d;
                    if (part == 0) {            // Q -> fp16 planes, pre-scaled 1/8
                        __half h0, l0, h1, l1;
                        split2_fp16(val.x * 0.125f, h0, l0);
                        split2_fp16(val.y * 0.125f, h1, l1);
                        *(__half2*)&g_qh[off] = __halves2half2(h0, h1);
                        *(__half2*)&g_ql[off] = __halves2half2(l0, l1);
                    } else if (part == 1) {     // K -> fp16 planes
                        __half h0, l0, h1, l1;
                        split2_fp16(val.x, h0, l0);
                        split2_fp16(val.y, h1, l1);
                        *(__half2*)&g_kh[off] = __halves2half2(h0, h1);
                        *(__half2*)&g_kl[off] = __halves2half2(l0, l1);
                    } else {                    // V -> fp32 (transposed next)
                        *(float2*)&g_v[off] = val;
                    }
                } else {
                    *(float2*)&Cparam[(size_t)m * cC + n] = val;
                }
            }
        }
    }
}

// -------------------- V transpose: g_v [bh][T][D] -> single fp16 plane [bh][D][T] --------
__global__ void transpose_v_kernel() {
    __shared__ float tile[32][33];
    int bh = blockIdx.z;
    int t0 = blockIdx.x * 32, d0 = blockIdx.y * 32;
    int tx = threadIdx.x, ty = threadIdx.y;
#pragma unroll
    for (int i = 0; i < 32; i += 8)
        tile[ty + i][tx] = g_v[((size_t)bh * cT + t0 + ty + i) * cD + d0 + tx];
    __syncthreads();
#pragma unroll
    for (int i = 0; i < 32; i += 8) {
        size_t off = ((size_t)bh * cD + d0 + ty + i) * cT + t0 + tx;
        g_vth[off] = __float2half_rn(tile[tx][ty + i]);
    }
}

// -------------------- fp16 flash attention, single-plane V, double-buffered ----------
// CTA: 128 q-rows, 8 warps x 16 rows; K-tile 64. Pre-split fp16 planes in gmem.
constexpr int HST = 72;                        // half stride per row (144 B)
constexpr int QPL2 = 128 * HST;                // halves per Q plane
constexpr int KPL2 = 64 * HST;                 // halves per K/V plane
constexpr int KVBUF = 3 * KPL2;                // kh, kl, vh
constexpr int ATTN_SMEM = (2 * QPL2 + 2 * KVBUF + 2 * QPL2) * 2;   // 129024 B

__global__ __launch_bounds__(256) void flash_attn_f16_kernel() {
    extern __shared__ __half smh[];

    const int tid = threadIdx.x;
    const int lane = tid & 31, wid = tid >> 5;
    const int g = lane >> 2, l4 = lane & 3;
    const int bh = blockIdx.y;
    const int qt = (int)gridDim.x - 1 - (int)blockIdx.x;   // big tiles first
    const int m0 = wid * 16;

    const uint32_t sbase = (uint32_t)__cvta_generic_to_shared(smh);
    const uint32_t qhB = sbase, qlB = sbase + QPL2 * 2;
    const uint32_t kv0B = qlB + QPL2 * 2;
    const uint32_t phB = kv0B + 2 * KVBUF * 2, plB = phB + QPL2 * 2;
    __half* PH = smh + 2 * QPL2 + 2 * KVBUF;
    __half* PL = PH + QPL2;

    const int aRow = (lane & 7) + ((lane >> 3) & 1) * 8;
    const int aColB = ((lane >> 4) & 1) * 16;
    const int bRow = (lane & 7) + ((lane >> 4) & 1) * 8;
    const int bColB = ((lane >> 3) & 1) * 16;

    // KV stage loader: 3 planes x 64 rows x 8 chunks = 1536 chunks, 6/thread
    auto load_kv = [&](int kt, int buf) {
        uint32_t dst0 = kv0B + (uint32_t)(buf * KVBUF * 2);
        const __half* kp_h = g_kh + ((size_t)bh * cT + kt * 64) * cD;
        const __half* kp_l = g_kl + ((size_t)bh * cT + kt * 64) * cD;
        const __half* vp_h = g_vth + (size_t)bh * cD * cT + kt * 64;
#pragma unroll
        for (int i = 0; i < 6; i++) {
            int id = tid + i * 256;               // 0..1535
            int p = id >> 9, rem = id & 511;
            int r = rem >> 3, c = rem & 7;
            uint32_t dst = dst0 + (uint32_t)(p * KPL2 * 2 + r * 144 + c * 16);
            const __half* gp;
            if (p == 0) gp = kp_h + (size_t)r * cD + c * 8;
            else if (p == 1) gp = kp_l + (size_t)r * cD + c * 8;
            else gp = vp_h + (size_t)r * cT + c * 8;
            cp_async16(dst, gp);
        }
        cp_commit();
    };

    // prologue: Q planes (2048 chunks) + KV stage 0, one commit group
    {
        const __half* qp_h = g_qh + ((size_t)bh * cT + qt * 128) * cD;
        const __half* qp_l = g_ql + ((size_t)bh * cT + qt * 128) * cD;
#pragma unroll
        for (int i = 0; i < 8; i++) {
            int id = tid + i * 256;               // 0..2047
            int p = id >> 10, rem = id & 1023;
            int r = rem >> 3, c = rem & 7;
            uint32_t dst = (p == 0 ? qhB : qlB) + (uint32_t)(r * 144 + c * 16);
            const __half* gp = (p == 0 ? qp_h : qp_l) + (size_t)r * cD + c * 8;
            cp_async16(dst, gp);
        }
    }
    load_kv(0, 0);   // commits Q + KV0 together

    float m_i[2] = {-1e30f, -1e30f}, l_i[2] = {0.f, 0.f};
    float O[8][4];
#pragma unroll
    for (int nt = 0; nt < 8; nt++)
#pragma unroll
        for (int c = 0; c < 4; c++) O[nt][c] = 0.f;

    const int ktmax = 2 * qt + 1;
    for (int kt = 0; kt <= ktmax; kt++) {
        if (kt + 1 <= ktmax) {
            load_kv(kt + 1, (kt + 1) & 1);
            cp_wait<1>();
        } else {
            cp_wait<0>();
        }
        __syncthreads();

        const uint32_t kvB = kv0B + (uint32_t)((kt & 1) * KVBUF * 2);
        const uint32_t khB = kvB, klB = kvB + KPL2 * 2;
        const uint32_t vhB = kvB + 2 * KPL2 * 2;

        const bool active = (kt * 64 <= qt * 128 + m0 + 15);
        if (active) {
            // ---- S = Q K^T (3-MMA fp16 2-plane) ----
            float s[8][4];
#pragma unroll
            for (int nt = 0; nt < 8; nt++)
#pragma unroll
                for (int c = 0; c < 4; c++) s[nt][c] = 0.f;

#pragma unroll
            for (int kcp = 0; kcp < 4; kcp++) {
                const int kB = kcp * 32;
                uint32_t aH[4], aL[4];
                ldsm4(qhB + 2u * ((m0 + aRow) * HST) + kB + aColB, aH);
                ldsm4(qlB + 2u * ((m0 + aRow) * HST) + kB + aColB, aL);
                uint32_t bfh[8][2], bfl[8][2];
#pragma unroll
                for (int np = 0; np < 4; np++) {
                    uint32_t t4[4];
                    ldsm4(khB + 2u * ((np * 16 + bRow) * HST) + kB + bColB, t4);
                    bfh[2 * np][0] = t4[0]; bfh[2 * np][1] = t4[1];
                    bfh[2 * np + 1][0] = t4[2]; bfh[2 * np + 1][1] = t4[3];
                    ldsm4(klB + 2u * ((np * 16 + bRow) * HST) + kB + bColB, t4);
                    bfl[2 * np][0] = t4[0]; bfl[2 * np][1] = t4[1];
                    bfl[2 * np + 1][0] = t4[2]; bfl[2 * np + 1][1] = t4[3];
                }
#pragma unroll
                for (int nt = 0; nt < 8; nt++) {
                    mma_f16(s[nt], aL, bfh[nt]);      // Ql.Kh
                    mma_f16(s[nt], aH, bfl[nt]);      // Qh.Kl
                    mma_f16(s[nt], aH, bfh[nt]);      // Qh.Kh
                }
            }

            // ---- causal mask ----
            if (kt >= 2 * qt) {
                int q0 = qt * 128 + m0 + g, q1 = q0 + 8;
#pragma unroll
                for (int nt = 0; nt < 8; nt++) {
                    int kc0 = kt * 64 + nt * 8 + 2 * l4;
                    if (kc0 > q0) s[nt][0] = -1e30f;
                    if (kc0 + 1 > q0) s[nt][1] = -1e30f;
                    if (kc0 > q1) s[nt][2] = -1e30f;
                    if (kc0 + 1 > q1) s[nt][3] = -1e30f;
                }
            }

            // ---- online softmax ----
#pragma unroll
            for (int r = 0; r < 2; r++) {
                float rm = -1e30f;
#pragma unroll
                for (int nt = 0; nt < 8; nt++)
                    rm = fmaxf(rm, fmaxf(s[nt][2 * r], s[nt][2 * r + 1]));
                rm = fmaxf(rm, __shfl_xor_sync(0xffffffffu, rm, 1));
                rm = fmaxf(rm, __shfl_xor_sync(0xffffffffu, rm, 2));
                float mnew = fmaxf(m_i[r], rm);
                float alpha = __expf(m_i[r] - mnew);
                float rs = 0.f;
#pragma unroll
                for (int nt = 0; nt < 8; nt++) {
                    s[nt][2 * r] = __expf(s[nt][2 * r] - mnew);
                    s[nt][2 * r + 1] = __expf(s[nt][2 * r + 1] - mnew);
                    rs += s[nt][2 * r] + s[nt][2 * r + 1];
                }
                rs += __shfl_xor_sync(0xffffffffu, rs, 1);
                rs += __shfl_xor_sync(0xffffffffu, rs, 2);
                l_i[r] = l_i[r] * alpha + rs;
                m_i[r] = mnew;
#pragma unroll
                for (int nt = 0; nt < 8; nt++) {
                    O[nt][2 * r] *= alpha;
                    O[nt][2 * r + 1] *= alpha;
                }
            }

            // ---- stage P (fp16 hi/lo) ----
#pragma unroll
            for (int nt = 0; nt < 8; nt++) {
                int col = nt * 8 + 2 * l4;
                __half h0, l0, h1, l1;
                split2_fp16(s[nt][0], h0, l0); split2_fp16(s[nt][1], h1, l1);
                *(__half2*)&PH[(m0 + g) * HST + col] = __halves2half2(h0, h1);
                *(__half2*)&PL[(m0 + g) * HST + col] = __halves2half2(l0, l1);
                split2_fp16(s[nt][2], h0, l0); split2_fp16(s[nt][3], h1, l1);
                *(__half2*)&PH[(m0 + g + 8) * HST + col] = __halves2half2(h0, h1);
                *(__half2*)&PL[(m0 + g + 8) * HST + col] = __halves2half2(l0, l1);
            }
            __syncwarp();   // P rows are warp-private

            // ---- O += P V (V single-plane: 2 MMAs) ----
#pragma unroll
            for (int kcp = 0; kcp < 4; kcp++) {
                const int kB = kcp * 32;
                uint32_t pH[4], pL[4];
                ldsm4(phB + 2u * ((m0 + aRow) * HST) + kB + aColB, pH);
                ldsm4(plB + 2u * ((m0 + aRow) * HST) + kB + aColB, pL);
#pragma unroll
                for (int np = 0; np < 4; np++) {
                    uint32_t th[4];
                    ldsm4(vhB + 2u * ((np * 16 + bRow) * HST) + kB + bColB, th);
                    uint32_t vh0[2] = {th[0], th[1]}, vh1[2] = {th[2], th[3]};
                    mma_f16(O[2 * np], pL, vh0);          // Pl.Vh
                    mma_f16(O[2 * np], pH, vh0);          // Ph.Vh
                    mma_f16(O[2 * np + 1], pL, vh1);
                    mma_f16(O[2 * np + 1], pH, vh1);
                }
            }
        }
        __syncthreads();   // all reads of this KV buffer done before refill
    }

    // ---- epilogue -> single fp16 plane for the output projection ----
    int b = bh >> 4, h = bh & 15;
    float inv0 = 1.0f / l_i[0], inv1 = 1.0f / l_i[1];
    int q0 = qt * 128 + m0 + g;
    size_t row0 = (size_t)(b * cT) + q0;
#pragma unroll
    for (int nt = 0; nt < 8; nt++) {
        int d = h * 64 + nt * 8 + 2 * l4;
        *(__half2*)&g_ah[row0 * cC + d] =
            __floats2half2_rn(O[nt][0] * inv0, O[nt][1] * inv0);
        *(__half2*)&g_ah[(row0 + 8) * cC + d] =
            __floats2half2_rn(O[nt][2] * inv1, O[nt][3] * inv1);
    }
}

// -------------------- launch --------------------
extern "C" void kernel_launch(void* const* d_in, const int* in_sizes, int n_in,
                              void* d_out, int out_size) {
    (void)in_sizes; (void)n_in; (void)out_size;
    const float* x = (const float*)d_in[0];
    const float* w_qkv = (const float*)d_in[1];
    const float* w_out = (const float*)d_in[2];
    float* out = (float*)d_out;

    abssum_partial_kernel<<<1024, 256>>>(w_qkv, cNWq);
    finalize_scale_kernel<<<1, 256>>>(1.0f / (float)cNWq);
    quantize_kernel<0><<<cNWq / 4 / 256, 256>>>(w_qkv, cNWq / 4);
    abssum_partial_kernel<<<1024, 256>>>(w_out, cNWo);
    finalize_scale_kernel<<<1, 256>>>(1.0f / (float)cNWo);
    quantize_kernel<1><<<cNWo / 4 / 256, 256>>>(w_out, cNWo / 4);

    split_x_kernel<<<cM * cK / 4 / 256, 256>>>(x);

    // qkv projection (fp16 2-plane; writes Q/K planes + V fp32)
    {
        constexpr int SM0 = 2 * 3 * APL_B;    // 61440
        cudaFuncSetAttribute(gemm_fp16_kernel<0, 2>,
                             cudaFuncAttributeMaxDynamicSharedMemorySize, SM0);
        dim3 grid(cNqkv / 128, cM / 128);
        gemm_fp16_kernel<0, 2><<<grid, 256, SM0>>>(nullptr);
    }

    // V transpose -> single fp16 plane
    {
        dim3 grid(cT / 32, cD / 32, cB * cH);
        transpose_v_kernel<<<grid, dim3(32, 8)>>>();
    }

    // fp16 tensor-core causal flash attention (single-plane V)
    {
        cudaFuncSetAttribute(flash_attn_f16_kernel,
                             cudaFuncAttributeMaxDynamicSharedMemorySize, ATTN_SMEM);
        dim3 grid(cT / 128, cB * cH);
        flash_attn_f16_kernel<<<grid, 256, ATTN_SMEM>>>();
    }

    // output projection (fp16 single-plane A)
    {
        constexpr int SM1 = 2 * 2 * APL_B;    // 40960
        cudaFuncSetAttribute(gemm_fp16_kernel<1, 1>,
                             cudaFuncAttributeMaxDynamicSharedMemorySize, SM1);
        dim3 grid(cC / 128, cM / 128);
        gemm_fp16_kernel<1, 1><<<grid, 256, SM1>>>(out);
    }
}

// round 16
// speedup vs baseline: 2.8677x; 1.1246x over previous
#include <cuda_runtime.h>
#include <cuda_fp16.h>
#include <cstdint>

// Problem constants
constexpr int cB = 4;
constexpr int cT = 2048;
constexpr int cC = 1024;
constexpr int cH = 16;
constexpr int cD = 64;
constexpr int cM = cB * cT;          // 8192
constexpr int cNqkv = 3 * cC;        // 3072
constexpr int cNWq = cNqkv * cC;
constexpr int cNWo = cC * cC;
constexpr int cK = 1024;
constexpr int cBHT = cB * cH * cT;   // 131072 rows of width 64

// -------------------- device scratch --------------------
__device__ float g_partial[1024];
__device__ float g_scale_inv;
__device__ __half g_wqh[cNWq];                 // ternary qkv weights (fp16, exact)
__device__ __half g_woh[cNWo];                 // ternary out-proj weights
__device__ __half g_xh[cM * cK], g_xl[cM * cK];   // x planes (fp16 hi/lo)
__device__ __half g_ah[cM * cK];               // attn-out plane (single, fp16)
__device__ __half g_qh[cBHT * cD], g_ql[cBHT * cD];   // Q planes [B,H,T,D], pre-scaled 1/8
__device__ __half g_kh[cBHT * cD], g_kl[cBHT * cD];   // K planes [B,H,T,D]
__device__ __half g_vth[cBHT * cD];            // V^T single plane [B,H,D,T]
__device__ float g_v[cBHT * cD];               // V fp32 [B,H,T,D] (for transpose)

// -------------------- absmean scale --------------------
__global__ void abssum_partial_kernel(const float* __restrict__ w, int n) {
    __shared__ float sd[256];
    int chunk = (n + (int)gridDim.x - 1) / (int)gridDim.x;
    int start = (int)blockIdx.x * chunk;
    int end = start + chunk; if (end > n) end = n;
    float s = 0.f;
    for (int i = start + (int)threadIdx.x; i < end; i += 256) s += fabsf(w[i]);
    sd[threadIdx.x] = s;
    __syncthreads();
    for (int o = 128; o > 0; o >>= 1) {
        if ((int)threadIdx.x < o) sd[threadIdx.x] += sd[threadIdx.x + o];
        __syncthreads();
    }
    if (threadIdx.x == 0) g_partial[blockIdx.x] = sd[0];
}

__global__ void finalize_scale_kernel(float inv_n) {
    __shared__ float sd[256];
    float s = 0.f;
    for (int i = threadIdx.x; i < 1024; i += 256) s += g_partial[i];
    sd[threadIdx.x] = s;
    __syncthreads();
    for (int o = 128; o > 0; o >>= 1) {
        if ((int)threadIdx.x < o) sd[threadIdx.x] += sd[threadIdx.x + o];
        __syncthreads();
    }
    if (threadIdx.x == 0) {
        float sc = fmaxf(sd[0] * inv_n, 1e-8f);
        g_scale_inv = 1.0f / sc;
    }
}

template <int WHICH>
__global__ void quantize_kernel(const float* __restrict__ w, int n4) {
    int i = (int)blockIdx.x * 256 + (int)threadIdx.x;
    if (i >= n4) return;
    float inv = g_scale_inv;
    float4 v = ((const float4*)w)[i];
    __half* dst = (WHICH == 0) ? g_wqh : g_woh;
    __half2* d2 = (__half2*)(dst + (size_t)i * 4);
    d2[0] = __floats2half2_rn(fminf(1.f, fmaxf(-1.f, rintf(v.x * inv))),
                              fminf(1.f, fmaxf(-1.f, rintf(v.y * inv))));
    d2[1] = __floats2half2_rn(fminf(1.f, fmaxf(-1.f, rintf(v.z * inv))),
                              fminf(1.f, fmaxf(-1.f, rintf(v.w * inv))));
}

// -------------------- helpers --------------------
__device__ __forceinline__ void cp_async16(uint32_t smem_addr, const void* gptr) {
    asm volatile("cp.async.cg.shared.global [%0], [%1], 16;\n" ::"r"(smem_addr), "l"(gptr));
}
__device__ __forceinline__ void cp_commit() { asm volatile("cp.async.commit_group;\n"); }
template <int N>
__device__ __forceinline__ void cp_wait() { asm volatile("cp.async.wait_group %0;\n" ::"n"(N)); }

__device__ __forceinline__ void split2_fp16(float a, __half& h, __half& l) {
    h = __float2half_rn(a);
    l = __float2half_rn(a - __half2float(h));
}
__device__ __forceinline__ void mma_f16(float* d, const uint32_t* a, const uint32_t* b) {
    asm volatile(
        "mma.sync.aligned.m16n8k16.row.col.f32.f16.f16.f32 "
        "{%0,%1,%2,%3}, {%4,%5,%6,%7}, {%8,%9}, {%0,%1,%2,%3};\n"
        : "+f"(d[0]), "+f"(d[1]), "+f"(d[2]), "+f"(d[3])
        : "r"(a[0]), "r"(a[1]), "r"(a[2]), "r"(a[3]), "r"(b[0]), "r"(b[1]));
}
__device__ __forceinline__ void ldsm4(uint32_t addr, uint32_t* r) {
    asm volatile("ldmatrix.sync.aligned.m8n8.x4.shared.b16 {%0,%1,%2,%3}, [%4];\n"
                 : "=r"(r[0]), "=r"(r[1]), "=r"(r[2]), "=r"(r[3]) : "r"(addr));
}

// -------------------- split x into 2 fp16 planes --------------------
__global__ void split_x_kernel(const float* __restrict__ x) {
    int i = (int)blockIdx.x * 256 + (int)threadIdx.x;     // float4 index
    float4 v = ((const float4*)x)[i];
    __half h[4], l[4];
    split2_fp16(v.x, h[0], l[0]);
    split2_fp16(v.y, h[1], l[1]);
    split2_fp16(v.z, h[2], l[2]);
    split2_fp16(v.w, h[3], l[3]);
    size_t o2 = (size_t)i * 2;
    ((__half2*)g_xh)[o2] = __halves2half2(h[0], h[1]);
    ((__half2*)g_xh)[o2 + 1] = __halves2half2(h[2], h[3]);
    ((__half2*)g_xl)[o2] = __halves2half2(l[0], l[1]);
    ((__half2*)g_xl)[o2 + 1] = __halves2half2(l[2], l[3]);
}

// -------------------- fp16 tensor-core GEMM (NPL A-planes) --------------------
// MODE 0: V-output tiles (n0 >= 2C) run single-plane (V precision is fp16-capped anyway)
constexpr int APL_B = 128 * 80;               // one plane, bytes

template <int MODE, int NPL>
__global__ __launch_bounds__(256) void gemm_fp16_kernel(float* __restrict__ Cparam) {
    constexpr int STG = (NPL + 1) * APL_B;     // A planes + B plane per stage
    extern __shared__ char smc[];
    const __half* Ah = (MODE == 0) ? g_xh : g_ah;
    const __half* Al = (MODE == 0) ? g_xl : g_ah;   // unused when NPL==1
    const __half* Wh = (MODE == 0) ? g_wqh : g_woh;

    const int tid = threadIdx.x;
    const int lane = tid & 31, wid = tid >> 5;
    const int warp_m = (wid >> 1) * 32;
    const int warp_n = (wid & 1) * 64;
    const int g = lane >> 2, l4 = lane & 3;

    const int m0 = (int)blockIdx.y * 128;
    const int n0 = (int)blockIdx.x * 128;
    const bool vtile = (MODE == 0) && (n0 >= 2 * cC);   // V-only tile -> single plane

    float acc[2][8][4];
#pragma unroll
    for (int mt = 0; mt < 2; mt++)
#pragma unroll
        for (int nt = 0; nt < 8; nt++)
#pragma unroll
            for (int c = 0; c < 4; c++) acc[mt][nt][c] = 0.f;

    const uint32_t sbase = (uint32_t)__cvta_generic_to_shared(smc);

    const int aRow = (lane & 7) + ((lane >> 3) & 1) * 8;
    const int aColB = ((lane >> 4) & 1) * 16;
    const int bRow = (lane & 7) + ((lane >> 4) & 1) * 8;
    const int bColB = ((lane >> 3) & 1) * 16;

    auto load_stage = [&](int s) {
        uint32_t stg = sbase + (uint32_t)((s & 1) * STG);
        int k0 = s * 32;
#pragma unroll
        for (int i = 0; i < 2 * (NPL + 1); i++) {
            int id = tid + i * 256;                   // 0..512*(NPL+1)-1
            if (id < NPL * 512) {
                int p = id >> 9, rem = id & 511;
                int r = rem >> 2, c = rem & 3;
                if (p == 1 && vtile) continue;        // V tile: no low plane
                const __half* src = (p == 0) ? Ah : Al;
                cp_async16(stg + p * APL_B + r * 80 + c * 16,
                           src + (size_t)(m0 + r) * cK + k0 + c * 8);
            } else {
                int id2 = id - NPL * 512;
                int r = id2 >> 2, c = id2 & 3;
                cp_async16(stg + NPL * APL_B + r * 80 + c * 16,
                           Wh + (size_t)(n0 + r) * cK + k0 + c * 8);
            }
        }
        cp_commit();
    };

    const int NS = cK / 32;
    load_stage(0);

    for (int s = 0; s < NS; s++) {
        if (s + 1 < NS) {
            load_stage(s + 1);
            cp_wait<1>();
        } else {
            cp_wait<0>();
        }
        __syncthreads();

        uint32_t stg = sbase + (uint32_t)((s & 1) * STG);
        uint32_t bStg = stg + NPL * APL_B;
#pragma unroll
        for (int ks = 0; ks < 2; ks++) {
            const int kB = ks * 32;
            uint32_t af[2][NPL][4];
#pragma unroll
            for (int mt = 0; mt < 2; mt++) {
                ldsm4(stg + (warp_m + mt * 16 + aRow) * 80 + kB + aColB, af[mt][0]);
                if (NPL == 2 && !vtile)
                    ldsm4(stg + APL_B + (warp_m + mt * 16 + aRow) * 80 + kB + aColB,
                          af[mt][NPL - 1]);
            }
            uint32_t bf[8][2];
#pragma unroll
            for (int np = 0; np < 4; np++) {
                uint32_t t4[4];
                ldsm4(bStg + (warp_n + np * 16 + bRow) * 80 + kB + bColB, t4);
                bf[2 * np][0] = t4[0]; bf[2 * np][1] = t4[1];
                bf[2 * np + 1][0] = t4[2]; bf[2 * np + 1][1] = t4[3];
            }
#pragma unroll
            for (int mt = 0; mt < 2; mt++)
#pragma unroll
                for (int nt = 0; nt < 8; nt++) {
                    if (NPL == 2 && !vtile) mma_f16(acc[mt][nt], af[mt][NPL - 1], bf[nt]);
                    mma_f16(acc[mt][nt], af[mt][0], bf[nt]);
                }
        }
        __syncthreads();
    }

#pragma unroll
    for (int mt = 0; mt < 2; mt++) {
#pragma unroll
        for (int h8 = 0; h8 < 2; h8++) {
            int m = m0 + warp_m + mt * 16 + g + h8 * 8;
#pragma unroll
            for (int nt = 0; nt < 8; nt++) {
                int n = n0 + warp_n + nt * 8 + l4 * 2;
                float2 val = make_float2(acc[mt][nt][h8 * 2 + 0], acc[mt][nt][h8 * 2 + 1]);
                if (MODE == 0) {
                    int b = m >> 11;
                    int t = m & 2047;
                    int part = n >> 10;
                    int c = n & 1023;
                    int hh = c >> 6;
                    int d = c & 63;
                    size_t off = ((size_t)(b * cH + hh) * cT + t) * cD + d;
                    if (part == 0) {            // Q -> fp16 planes, pre-scaled 1/8
                        __half h0, l0, h1, l1;
                        split2_fp16(val.x * 0.125f, h0, l0);
                        split2_fp16(val.y * 0.125f, h1, l1);
                        *(__half2*)&g_qh[off] = __halves2half2(h0, h1);
                        *(__half2*)&g_ql[off] = __halves2half2(l0, l1);
                    } else if (part == 1) {     // K -> fp16 planes
                        __half h0, l0, h1, l1;
                        split2_fp16(val.x, h0, l0);
                        split2_fp16(val.y, h1, l1);
                        *(__half2*)&g_kh[off] = __halves2half2(h0, h1);
                        *(__half2*)&g_kl[off] = __halves2half2(l0, l1);
                    } else {                    // V -> fp32 (transposed next)
                        *(float2*)&g_v[off] = val;
                    }
                } else {
                    *(float2*)&Cparam[(size_t)m * cC + n] = val;
                }
            }
        }
    }
}

// -------------------- V transpose: g_v [bh][T][D] -> single fp16 plane [bh][D][T] --------
__global__ void transpose_v_kernel() {
    __shared__ float tile[32][33];
    int bh = blockIdx.z;
    int t0 = blockIdx.x * 32, d0 = blockIdx.y * 32;
    int tx = threadIdx.x, ty = threadIdx.y;
#pragma unroll
    for (int i = 0; i < 32; i += 8)
        tile[ty + i][tx] = g_v[((size_t)bh * cT + t0 + ty + i) * cD + d0 + tx];
    __syncthreads();
#pragma unroll
    for (int i = 0; i < 32; i += 8) {
        size_t off = ((size_t)bh * cD + d0 + ty + i) * cT + t0 + tx;
        g_vth[off] = __float2half_rn(tile[tx][ty + i]);
    }
}

// -------------------- fp16 flash attention: 2-plane S, 1-plane PV ------------------
// CTA: 128 q-rows, 8 warps x 16 rows; K-tile 64. Pre-split fp16 planes in gmem.
constexpr int HST = 72;                        // half stride per row (144 B)
constexpr int QPL2 = 128 * HST;                // halves per Q plane
constexpr int KPL2 = 64 * HST;                 // halves per K/V plane
constexpr int KVBUF = 3 * KPL2;                // kh, kl, vh
constexpr int ATTN_SMEM = (2 * QPL2 + 2 * KVBUF + QPL2) * 2;   // 110592 B

__global__ __launch_bounds__(256) void flash_attn_f16_kernel() {
    extern __shared__ __half smh[];

    const int tid = threadIdx.x;
    const int lane = tid & 31, wid = tid >> 5;
    const int g = lane >> 2, l4 = lane & 3;
    const int bh = blockIdx.y;
    const int qt = (int)gridDim.x - 1 - (int)blockIdx.x;   // big tiles first
    const int m0 = wid * 16;

    const uint32_t sbase = (uint32_t)__cvta_generic_to_shared(smh);
    const uint32_t qhB = sbase, qlB = sbase + QPL2 * 2;
    const uint32_t kv0B = qlB + QPL2 * 2;
    const uint32_t phB = kv0B + 2 * KVBUF * 2;
    __half* PH = smh + 2 * QPL2 + 2 * KVBUF;

    const int aRow = (lane & 7) + ((lane >> 3) & 1) * 8;
    const int aColB = ((lane >> 4) & 1) * 16;
    const int bRow = (lane & 7) + ((lane >> 4) & 1) * 8;
    const int bColB = ((lane >> 3) & 1) * 16;

    // KV stage loader: 3 planes x 64 rows x 8 chunks = 1536 chunks, 6/thread
    auto load_kv = [&](int kt, int buf) {
        uint32_t dst0 = kv0B + (uint32_t)(buf * KVBUF * 2);
        const __half* kp_h = g_kh + ((size_t)bh * cT + kt * 64) * cD;
        const __half* kp_l = g_kl + ((size_t)bh * cT + kt * 64) * cD;
        const __half* vp_h = g_vth + (size_t)bh * cD * cT + kt * 64;
#pragma unroll
        for (int i = 0; i < 6; i++) {
            int id = tid + i * 256;               // 0..1535
            int p = id >> 9, rem = id & 511;
            int r = rem >> 3, c = rem & 7;
            uint32_t dst = dst0 + (uint32_t)(p * KPL2 * 2 + r * 144 + c * 16);
            const __half* gp;
            if (p == 0) gp = kp_h + (size_t)r * cD + c * 8;
            else if (p == 1) gp = kp_l + (size_t)r * cD + c * 8;
            else gp = vp_h + (size_t)r * cT + c * 8;
            cp_async16(dst, gp);
        }
        cp_commit();
    };

    // prologue: Q planes (2048 chunks) + KV stage 0, one commit group
    {
        const __half* qp_h = g_qh + ((size_t)bh * cT + qt * 128) * cD;
        const __half* qp_l = g_ql + ((size_t)bh * cT + qt * 128) * cD;
#pragma unroll
        for (int i = 0; i < 8; i++) {
            int id = tid + i * 256;               // 0..2047
            int p = id >> 10, rem = id & 1023;
            int r = rem >> 3, c = rem & 7;
            uint32_t dst = (p == 0 ? qhB : qlB) + (uint32_t)(r * 144 + c * 16);
            const __half* gp = (p == 0 ? qp_h : qp_l) + (size_t)r * cD + c * 8;
            cp_async16(dst, gp);
        }
    }
    load_kv(0, 0);   // commits Q + KV0 together

    float m_i[2] = {-1e30f, -1e30f}, l_i[2] = {0.f, 0.f};
    float O[8][4];
#pragma unroll
    for (int nt = 0; nt < 8; nt++)
#pragma unroll
        for (int c = 0; c < 4; c++) O[nt][c] = 0.f;

    const int ktmax = 2 * qt + 1;
    for (int kt = 0; kt <= ktmax; kt++) {
        if (kt + 1 <= ktmax) {
            load_kv(kt + 1, (kt + 1) & 1);
            cp_wait<1>();
        } else {
            cp_wait<0>();
        }
        __syncthreads();

        const uint32_t kvB = kv0B + (uint32_t)((kt & 1) * KVBUF * 2);
        const uint32_t khB = kvB, klB = kvB + KPL2 * 2;
        const uint32_t vhB = kvB + 2 * KPL2 * 2;

        const bool active = (kt * 64 <= qt * 128 + m0 + 15);
        if (active) {
            // ---- S = Q K^T (3-MMA fp16 2-plane) ----
            float s[8][4];
#pragma unroll
            for (int nt = 0; nt < 8; nt++)
#pragma unroll
                for (int c = 0; c < 4; c++) s[nt][c] = 0.f;

#pragma unroll
            for (int kcp = 0; kcp < 4; kcp++) {
                const int kB = kcp * 32;
                uint32_t aH[4], aL[4];
                ldsm4(qhB + 2u * ((m0 + aRow) * HST) + kB + aColB, aH);
                ldsm4(qlB + 2u * ((m0 + aRow) * HST) + kB + aColB, aL);
                uint32_t bfh[8][2], bfl[8][2];
#pragma unroll
                for (int np = 0; np < 4; np++) {
                    uint32_t t4[4];
                    ldsm4(khB + 2u * ((np * 16 + bRow) * HST) + kB + bColB, t4);
                    bfh[2 * np][0] = t4[0]; bfh[2 * np][1] = t4[1];
                    bfh[2 * np + 1][0] = t4[2]; bfh[2 * np + 1][1] = t4[3];
                    ldsm4(klB + 2u * ((np * 16 + bRow) * HST) + kB + bColB, t4);
                    bfl[2 * np][0] = t4[0]; bfl[2 * np][1] = t4[1];
                    bfl[2 * np + 1][0] = t4[2]; bfl[2 * np + 1][1] = t4[3];
                }
#pragma unroll
                for (int nt = 0; nt < 8; nt++) {
                    mma_f16(s[nt], aL, bfh[nt]);      // Ql.Kh
                    mma_f16(s[nt], aH, bfl[nt]);      // Qh.Kl
                    mma_f16(s[nt], aH, bfh[nt]);      // Qh.Kh
                }
            }

            // ---- causal mask ----
            if (kt >= 2 * qt) {
                int q0 = qt * 128 + m0 + g, q1 = q0 + 8;
#pragma unroll
                for (int nt = 0; nt < 8; nt++) {
                    int kc0 = kt * 64 + nt * 8 + 2 * l4;
                    if (kc0 > q0) s[nt][0] = -1e30f;
                    if (kc0 + 1 > q0) s[nt][1] = -1e30f;
                    if (kc0 > q1) s[nt][2] = -1e30f;
                    if (kc0 + 1 > q1) s[nt][3] = -1e30f;
                }
            }

            // ---- online softmax ----
#pragma unroll
            for (int r = 0; r < 2; r++) {
                float rm = -1e30f;
#pragma unroll
                for (int nt = 0; nt < 8; nt++)
                    rm = fmaxf(rm, fmaxf(s[nt][2 * r], s[nt][2 * r + 1]));
                rm = fmaxf(rm, __shfl_xor_sync(0xffffffffu, rm, 1));
                rm = fmaxf(rm, __shfl_xor_sync(0xffffffffu, rm, 2));
                float mnew = fmaxf(m_i[r], rm);
                float alpha = __expf(m_i[r] - mnew);
                float rs = 0.f;
#pragma unroll
                for (int nt = 0; nt < 8; nt++) {
                    s[nt][2 * r] = __expf(s[nt][2 * r] - mnew);
                    s[nt][2 * r + 1] = __expf(s[nt][2 * r + 1] - mnew);
                    rs += s[nt][2 * r] + s[nt][2 * r + 1];
                }
                rs += __shfl_xor_sync(0xffffffffu, rs, 1);
                rs += __shfl_xor_sync(0xffffffffu, rs, 2);
                l_i[r] = l_i[r] * alpha + rs;
                m_i[r] = mnew;
#pragma unroll
                for (int nt = 0; nt < 8; nt++) {
                    O[nt][2 * r] *= alpha;
                    O[nt][2 * r + 1] *= alpha;
                }
            }

            // ---- stage P (single fp16 plane) ----
#pragma unroll
            for (int nt = 0; nt < 8; nt++) {
                int col = nt * 8 + 2 * l4;
                *(__half2*)&PH[(m0 + g) * HST + col] =
                    __floats2half2_rn(s[nt][0], s[nt][1]);
                *(__half2*)&PH[(m0 + g + 8) * HST + col] =
                    __floats2half2_rn(s[nt][2], s[nt][3]);
            }
            __syncwarp();   // P rows are warp-private

            // ---- O += P V (1 MMA: Ph.Vh) ----
#pragma unroll
            for (int kcp = 0; kcp < 4; kcp++) {
                const int kB = kcp * 32;
                uint32_t pH[4];
                ldsm4(phB + 2u * ((m0 + aRow) * HST) + kB + aColB, pH);
#pragma unroll
                for (int np = 0; np < 4; np++) {
                    uint32_t th[4];
                    ldsm4(vhB + 2u * ((np * 16 + bRow) * HST) + kB + bColB, th);
                    uint32_t vh0[2] = {th[0], th[1]}, vh1[2] = {th[2], th[3]};
                    mma_f16(O[2 * np], pH, vh0);
                    mma_f16(O[2 * np + 1], pH, vh1);
                }
            }
        }
        __syncthreads();   // all reads of this KV buffer done before refill
    }

    // ---- epilogue -> single fp16 plane for the output projection ----
    int b = bh >> 4, h = bh & 15;
    float inv0 = 1.0f / l_i[0], inv1 = 1.0f / l_i[1];
    int q0 = qt * 128 + m0 + g;
    size_t row0 = (size_t)(b * cT) + q0;
#pragma unroll
    for (int nt = 0; nt < 8; nt++) {
        int d = h * 64 + nt * 8 + 2 * l4;
        *(__half2*)&g_ah[row0 * cC + d] =
            __floats2half2_rn(O[nt][0] * inv0, O[nt][1] * inv0);
        *(__half2*)&g_ah[(row0 + 8) * cC + d] =
            __floats2half2_rn(O[nt][2] * inv1, O[nt][3] * inv1);
    }
}

// -------------------- launch --------------------
extern "C" void kernel_launch(void* const* d_in, const int* in_sizes, int n_in,
                              void* d_out, int out_size) {
    (void)in_sizes; (void)n_in; (void)out_size;
    const float* x = (const float*)d_in[0];
    const float* w_qkv = (const float*)d_in[1];
    const float* w_out = (const float*)d_in[2];
    float* out = (float*)d_out;

    abssum_partial_kernel<<<1024, 256>>>(w_qkv, cNWq);
    finalize_scale_kernel<<<1, 256>>>(1.0f / (float)cNWq);
    quantize_kernel<0><<<cNWq / 4 / 256, 256>>>(w_qkv, cNWq / 4);
    abssum_partial_kernel<<<1024, 256>>>(w_out, cNWo);
    finalize_scale_kernel<<<1, 256>>>(1.0f / (float)cNWo);
    quantize_kernel<1><<<cNWo / 4 / 256, 256>>>(w_out, cNWo / 4);

    split_x_kernel<<<cM * cK / 4 / 256, 256>>>(x);

    // qkv projection (fp16 2-plane; V tiles 1-plane)
    {
        constexpr int SM0 = 2 * 3 * APL_B;    // 61440
        cudaFuncSetAttribute(gemm_fp16_kernel<0, 2>,
                             cudaFuncAttributeMaxDynamicSharedMemorySize, SM0);
        dim3 grid(cNqkv / 128, cM / 128);
        gemm_fp16_kernel<0, 2><<<grid, 256, SM0>>>(nullptr);
    }

    // V transpose -> single fp16 plane
    {
        dim3 grid(cT / 32, cD / 32, cB * cH);
        transpose_v_kernel<<<grid, dim3(32, 8)>>>();
    }

    // fp16 tensor-core causal flash attention (2-plane S, 1-plane PV)
    {
        cudaFuncSetAttribute(flash_attn_f16_kernel,
                             cudaFuncAttributeMaxDynamicSharedMemorySize, ATTN_SMEM);
        dim3 grid(cT / 128, cB * cH);
        flash_attn_f16_kernel<<<grid, 256, ATTN_SMEM>>>();
    }

    // output projection (fp16 single-plane A)
    {
        constexpr int SM1 = 2 * 2 * APL_B;    // 40960
        cudaFuncSetAttribute(gemm_fp16_kernel<1, 1>,
                             cudaFuncAttributeMaxDynamicSharedMemorySize, SM1);
        dim3 grid(cC / 128, cM / 128);
        gemm_fp16_kernel<1, 1><<<grid, 256, SM1>>>(out);
    }
}

// round 17
// speedup vs baseline: 2.9356x; 1.0237x over previous
#include <cuda_runtime.h>
#include <cuda_fp16.h>
#include <cstdint>

// Problem constants
constexpr int cB = 4;
constexpr int cT = 2048;
constexpr int cC = 1024;
constexpr int cH = 16;
constexpr int cD = 64;
constexpr int cM = cB * cT;          // 8192
constexpr int cNqkv = 3 * cC;        // 3072
constexpr int cNWq = cNqkv * cC;
constexpr int cNWo = cC * cC;
constexpr int cK = 1024;
constexpr int cBHT = cB * cH * cT;   // 131072 rows of width 64

constexpr float QSCALE = 0.18033688011112042f;   // log2(e)/8 — exp2-domain softmax

// -------------------- device scratch --------------------
__device__ float g_partial[2048];
__device__ float g_scale_inv2[2];
__device__ __half g_wqh[cNWq];                 // ternary qkv weights (fp16, exact)
__device__ __half g_woh[cNWo];                 // ternary out-proj weights
__device__ __half g_xh[cM * cK], g_xl[cM * cK];   // x planes (fp16 hi/lo)
__device__ __half g_ah[cM * cK];               // attn-out plane (single, fp16)
__device__ __half g_qh[cBHT * cD], g_ql[cBHT * cD];   // Q planes [B,H,T,D], pre-scaled
__device__ __half g_kh[cBHT * cD], g_kl[cBHT * cD];   // K planes [B,H,T,D]
__device__ __half g_vh[cBHT * cD];             // V single plane [B,H,T,D] (row-major!)

// -------------------- fused absmean scale (both weights) --------------------
__global__ void abssum2_kernel(const float* __restrict__ w0, const float* __restrict__ w1) {
    __shared__ float sd[256];
    int which = blockIdx.y;
    const float* w = which ? w1 : w0;
    int n = which ? cNWo : cNWq;
    int chunk = (n + 1023) / 1024;
    int start = (int)blockIdx.x * chunk;
    int end = start + chunk; if (end > n) end = n;
    float s = 0.f;
    for (int i = start + (int)threadIdx.x; i < end; i += 256) s += fabsf(w[i]);
    sd[threadIdx.x] = s;
    __syncthreads();
    for (int o = 128; o > 0; o >>= 1) {
        if ((int)threadIdx.x < o) sd[threadIdx.x] += sd[threadIdx.x + o];
        __syncthreads();
    }
    if (threadIdx.x == 0) g_partial[which * 1024 + blockIdx.x] = sd[0];
}

__global__ void finalize2_kernel() {
    __shared__ float sd[256];
    int which = blockIdx.x;
    float s = 0.f;
    for (int i = threadIdx.x; i < 1024; i += 256) s += g_partial[which * 1024 + i];
    sd[threadIdx.x] = s;
    __syncthreads();
    for (int o = 128; o > 0; o >>= 1) {
        if ((int)threadIdx.x < o) sd[threadIdx.x] += sd[threadIdx.x + o];
        __syncthreads();
    }
    if (threadIdx.x == 0) {
        float inv_n = which ? (1.0f / (float)cNWo) : (1.0f / (float)cNWq);
        float sc = fmaxf(sd[0] * inv_n, 1e-8f);
        g_scale_inv2[which] = 1.0f / sc;
    }
}

__global__ void quantize_both_kernel(const float* __restrict__ w0,
                                     const float* __restrict__ w1) {
    int i = (int)blockIdx.x * 256 + (int)threadIdx.x;
    const int nq4 = cNWq / 4;
    bool second = (i >= nq4);
    const float* w = second ? w1 : w0;
    __half* dst = second ? g_woh : g_wqh;
    int j = second ? (i - nq4) : i;
    float inv = g_scale_inv2[second ? 1 : 0];
    float4 v = ((const float4*)w)[j];
    __half2* d2 = (__half2*)(dst + (size_t)j * 4);
    d2[0] = __floats2half2_rn(fminf(1.f, fmaxf(-1.f, rintf(v.x * inv))),
                              fminf(1.f, fmaxf(-1.f, rintf(v.y * inv))));
    d2[1] = __floats2half2_rn(fminf(1.f, fmaxf(-1.f, rintf(v.z * inv))),
                              fminf(1.f, fmaxf(-1.f, rintf(v.w * inv))));
}

// -------------------- helpers --------------------
__device__ __forceinline__ void cp_async16(uint32_t smem_addr, const void* gptr) {
    asm volatile("cp.async.cg.shared.global [%0], [%1], 16;\n" ::"r"(smem_addr), "l"(gptr));
}
__device__ __forceinline__ void cp_commit() { asm volatile("cp.async.commit_group;\n"); }
template <int N>
__device__ __forceinline__ void cp_wait() { asm volatile("cp.async.wait_group %0;\n" ::"n"(N)); }

__device__ __forceinline__ void split2_fp16(float a, __half& h, __half& l) {
    h = __float2half_rn(a);
    l = __float2half_rn(a - __half2float(h));
}
__device__ __forceinline__ float fast_exp2(float x) {
    float r;
    asm("ex2.approx.f32 %0, %1;" : "=f"(r) : "f"(x));
    return r;
}
__device__ __forceinline__ void mma_f16(float* d, const uint32_t* a, const uint32_t* b) {
    asm volatile(
        "mma.sync.aligned.m16n8k16.row.col.f32.f16.f16.f32 "
        "{%0,%1,%2,%3}, {%4,%5,%6,%7}, {%8,%9}, {%0,%1,%2,%3};\n"
        : "+f"(d[0]), "+f"(d[1]), "+f"(d[2]), "+f"(d[3])
        : "r"(a[0]), "r"(a[1]), "r"(a[2]), "r"(a[3]), "r"(b[0]), "r"(b[1]));
}
__device__ __forceinline__ void ldsm4(uint32_t addr, uint32_t* r) {
    asm volatile("ldmatrix.sync.aligned.m8n8.x4.shared.b16 {%0,%1,%2,%3}, [%4];\n"
                 : "=r"(r[0]), "=r"(r[1]), "=r"(r[2]), "=r"(r[3]) : "r"(addr));
}
__device__ __forceinline__ void ldsm4t(uint32_t addr, uint32_t* r) {
    asm volatile("ldmatrix.sync.aligned.m8n8.x4.trans.shared.b16 {%0,%1,%2,%3}, [%4];\n"
                 : "=r"(r[0]), "=r"(r[1]), "=r"(r[2]), "=r"(r[3]) : "r"(addr));
}

// -------------------- split x into 2 fp16 planes --------------------
__global__ void split_x_kernel(const float* __restrict__ x) {
    int i = (int)blockIdx.x * 256 + (int)threadIdx.x;     // float4 index
    float4 v = ((const float4*)x)[i];
    __half h[4], l[4];
    split2_fp16(v.x, h[0], l[0]);
    split2_fp16(v.y, h[1], l[1]);
    split2_fp16(v.z, h[2], l[2]);
    split2_fp16(v.w, h[3], l[3]);
    size_t o2 = (size_t)i * 2;
    ((__half2*)g_xh)[o2] = __halves2half2(h[0], h[1]);
    ((__half2*)g_xh)[o2 + 1] = __halves2half2(h[2], h[3]);
    ((__half2*)g_xl)[o2] = __halves2half2(l[0], l[1]);
    ((__half2*)g_xl)[o2 + 1] = __halves2half2(l[2], l[3]);
}

// -------------------- fp16 tensor-core GEMM (NPL A-planes) --------------------
// MODE 0: V-output tiles (n0 >= 2C) run single-plane; V written directly as fp16 plane
constexpr int APL_B = 128 * 80;               // one plane, bytes

template <int MODE, int NPL>
__global__ __launch_bounds__(256) void gemm_fp16_kernel(float* __restrict__ Cparam) {
    constexpr int STG = (NPL + 1) * APL_B;     // A planes + B plane per stage
    extern __shared__ char smc[];
    const __half* Ah = (MODE == 0) ? g_xh : g_ah;
    const __half* Al = (MODE == 0) ? g_xl : g_ah;   // unused when NPL==1
    const __half* Wh = (MODE == 0) ? g_wqh : g_woh;

    const int tid = threadIdx.x;
    const int lane = tid & 31, wid = tid >> 5;
    const int warp_m = (wid >> 1) * 32;
    const int warp_n = (wid & 1) * 64;
    const int g = lane >> 2, l4 = lane & 3;

    const int m0 = (int)blockIdx.y * 128;
    const int n0 = (int)blockIdx.x * 128;
    const bool vtile = (MODE == 0) && (n0 >= 2 * cC);   // V-only tile -> single plane

    float acc[2][8][4];
#pragma unroll
    for (int mt = 0; mt < 2; mt++)
#pragma unroll
        for (int nt = 0; nt < 8; nt++)
#pragma unroll
            for (int c = 0; c < 4; c++) acc[mt][nt][c] = 0.f;

    const uint32_t sbase = (uint32_t)__cvta_generic_to_shared(smc);

    const int aRow = (lane & 7) + ((lane >> 3) & 1) * 8;
    const int aColB = ((lane >> 4) & 1) * 16;
    const int bRow = (lane & 7) + ((lane >> 4) & 1) * 8;
    const int bColB = ((lane >> 3) & 1) * 16;

    auto load_stage = [&](int s) {
        uint32_t stg = sbase + (uint32_t)((s & 1) * STG);
        int k0 = s * 32;
#pragma unroll
        for (int i = 0; i < 2 * (NPL + 1); i++) {
            int id = tid + i * 256;                   // 0..512*(NPL+1)-1
            if (id < NPL * 512) {
                int p = id >> 9, rem = id & 511;
                int r = rem >> 2, c = rem & 3;
                if (p == 1 && vtile) continue;        // V tile: no low plane
                const __half* src = (p == 0) ? Ah : Al;
                cp_async16(stg + p * APL_B + r * 80 + c * 16,
                           src + (size_t)(m0 + r) * cK + k0 + c * 8);
            } else {
                int id2 = id - NPL * 512;
                int r = id2 >> 2, c = id2 & 3;
                cp_async16(stg + NPL * APL_B + r * 80 + c * 16,
                           Wh + (size_t)(n0 + r) * cK + k0 + c * 8);
            }
        }
        cp_commit();
    };

    const int NS = cK / 32;
    load_stage(0);

    for (int s = 0; s < NS; s++) {
        if (s + 1 < NS) {
            load_stage(s + 1);
            cp_wait<1>();
        } else {
            cp_wait<0>();
        }
        __syncthreads();

        uint32_t stg = sbase + (uint32_t)((s & 1) * STG);
        uint32_t bStg = stg + NPL * APL_B;
#pragma unroll
        for (int ks = 0; ks < 2; ks++) {
            const int kB = ks * 32;
            uint32_t af[2][NPL][4];
#pragma unroll
            for (int mt = 0; mt < 2; mt++) {
                ldsm4(stg + (warp_m + mt * 16 + aRow) * 80 + kB + aColB, af[mt][0]);
                if (NPL == 2 && !vtile)
                    ldsm4(stg + APL_B + (warp_m + mt * 16 + aRow) * 80 + kB + aColB,
                          af[mt][NPL - 1]);
            }
            uint32_t bf[8][2];
#pragma unroll
            for (int np = 0; np < 4; np++) {
                uint32_t t4[4];
                ldsm4(bStg + (warp_n + np * 16 + bRow) * 80 + kB + bColB, t4);
                bf[2 * np][0] = t4[0]; bf[2 * np][1] = t4[1];
                bf[2 * np + 1][0] = t4[2]; bf[2 * np + 1][1] = t4[3];
            }
#pragma unroll
            for (int mt = 0; mt < 2; mt++)
#pragma unroll
                for (int nt = 0; nt < 8; nt++) {
                    if (NPL == 2 && !vtile) mma_f16(acc[mt][nt], af[mt][NPL - 1], bf[nt]);
                    mma_f16(acc[mt][nt], af[mt][0], bf[nt]);
                }
        }
        __syncthreads();
    }

#pragma unroll
    for (int mt = 0; mt < 2; mt++) {
#pragma unroll
        for (int h8 = 0; h8 < 2; h8++) {
            int m = m0 + warp_m + mt * 16 + g + h8 * 8;
#pragma unroll
            for (int nt = 0; nt < 8; nt++) {
                int n = n0 + warp_n + nt * 8 + l4 * 2;
                float2 val = make_float2(acc[mt][nt][h8 * 2 + 0], acc[mt][nt][h8 * 2 + 1]);
                if (MODE == 0) {
                    int b = m >> 11;
                    int t = m & 2047;
                    int part = n >> 10;
                    int c = n & 1023;
                    int hh = c >> 6;
                    int d = c & 63;
                    size_t off = ((size_t)(b * cH + hh) * cT + t) * cD + d;
                    if (part == 0) {            // Q -> fp16 planes, pre-scaled log2e/8
                        __half h0, l0, h1, l1;
                        split2_fp16(val.x * QSCALE, h0, l0);
                        split2_fp16(val.y * QSCALE, h1, l1);
                        *(__half2*)&g_qh[off] = __halves2half2(h0, h1);
                        *(__half2*)&g_ql[off] = __halves2half2(l0, l1);
                    } else if (part == 1) {     // K -> fp16 planes
                        __half h0, l0, h1, l1;
                        split2_fp16(val.x, h0, l0);
                        split2_fp16(val.y, h1, l1);
                        *(__half2*)&g_kh[off] = __halves2half2(h0, h1);
                        *(__half2*)&g_kl[off] = __halves2half2(l0, l1);
                    } else {                    // V -> single fp16 plane, row-major
                        *(__half2*)&g_vh[off] = __floats2half2_rn(val.x, val.y);
                    }
                } else {
                    *(float2*)&Cparam[(size_t)m * cC + n] = val;
                }
            }
        }
    }
}

// -------------------- fp16 flash attention: 2-plane S, 1-plane PV (trans-V) ----------
// CTA: 128 q-rows, 8 warps x 16 rows; K-tile 64. Pre-split fp16 planes in gmem.
constexpr int HST = 72;                        // half stride per row (144 B)
constexpr int QPL2 = 128 * HST;                // halves per Q plane
constexpr int KPL2 = 64 * HST;                 // halves per K/V plane
constexpr int KVBUF = 3 * KPL2;                // kh, kl, vh
constexpr int ATTN_SMEM = (2 * QPL2 + 2 * KVBUF + QPL2) * 2;   // 110592 B

__global__ __launch_bounds__(256) void flash_attn_f16_kernel() {
    extern __shared__ __half smh[];

    const int tid = threadIdx.x;
    const int lane = tid & 31, wid = tid >> 5;
    const int g = lane >> 2, l4 = lane & 3;
    const int bh = blockIdx.y;
    const int qt = (int)gridDim.x - 1 - (int)blockIdx.x;   // big tiles first
    const int m0 = wid * 16;

    const uint32_t sbase = (uint32_t)__cvta_generic_to_shared(smh);
    const uint32_t qhB = sbase, qlB = sbase + QPL2 * 2;
    const uint32_t kv0B = qlB + QPL2 * 2;
    const uint32_t phB = kv0B + 2 * KVBUF * 2;
    __half* PH = smh + 2 * QPL2 + 2 * KVBUF;

    const int aRow = (lane & 7) + ((lane >> 3) & 1) * 8;
    const int aColB = ((lane >> 4) & 1) * 16;
    const int bRow = (lane & 7) + ((lane >> 4) & 1) * 8;
    const int bColB = ((lane >> 3) & 1) * 16;

    // KV stage loader: kh, kl, vh — all row-major [key][d], identical addressing
    auto load_kv = [&](int kt, int buf) {
        uint32_t dst0 = kv0B + (uint32_t)(buf * KVBUF * 2);
        const __half* kp_h = g_kh + ((size_t)bh * cT + kt * 64) * cD;
        const __half* kp_l = g_kl + ((size_t)bh * cT + kt * 64) * cD;
        const __half* vp_h = g_vh + ((size_t)bh * cT + kt * 64) * cD;
#pragma unroll
        for (int i = 0; i < 6; i++) {
            int id = tid + i * 256;               // 0..1535
            int p = id >> 9, rem = id & 511;
            int r = rem >> 3, c = rem & 7;
            uint32_t dst = dst0 + (uint32_t)(p * KPL2 * 2 + r * 144 + c * 16);
            const __half* gp = (p == 0) ? kp_h : (p == 1) ? kp_l : vp_h;
            cp_async16(dst, gp + (size_t)r * cD + c * 8);
        }
        cp_commit();
    };

    // prologue: Q planes (2048 chunks) + KV stage 0, one commit group
    {
        const __half* qp_h = g_qh + ((size_t)bh * cT + qt * 128) * cD;
        const __half* qp_l = g_ql + ((size_t)bh * cT + qt * 128) * cD;
#pragma unroll
        for (int i = 0; i < 8; i++) {
            int id = tid + i * 256;               // 0..2047
            int p = id >> 10, rem = id & 1023;
            int r = rem >> 3, c = rem & 7;
            uint32_t dst = (p == 0 ? qhB : qlB) + (uint32_t)(r * 144 + c * 16);
            const __half* gp = (p == 0 ? qp_h : qp_l) + (size_t)r * cD + c * 8;
            cp_async16(dst, gp);
        }
    }
    load_kv(0, 0);   // commits Q + KV0 together

    float m_i[2] = {-1e30f, -1e30f}, l_i[2] = {0.f, 0.f};
    float O[8][4];
#pragma unroll
    for (int nt = 0; nt < 8; nt++)
#pragma unroll
        for (int c = 0; c < 4; c++) O[nt][c] = 0.f;

    const int ktmax = 2 * qt + 1;
    for (int kt = 0; kt <= ktmax; kt++) {
        if (kt + 1 <= ktmax) {
            load_kv(kt + 1, (kt + 1) & 1);
            cp_wait<1>();
        } else {
            cp_wait<0>();
        }
        __syncthreads();

        const uint32_t kvB = kv0B + (uint32_t)((kt & 1) * KVBUF * 2);
        const uint32_t khB = kvB, klB = kvB + KPL2 * 2;
        const uint32_t vhB = kvB + 2 * KPL2 * 2;

        const bool active = (kt * 64 <= qt * 128 + m0 + 15);
        if (active) {
            // ---- S = Q K^T (3-MMA fp16 2-plane), log2-domain logits ----
            float s[8][4];
#pragma unroll
            for (int nt = 0; nt < 8; nt++)
#pragma unroll
                for (int c = 0; c < 4; c++) s[nt][c] = 0.f;

#pragma unroll
            for (int kcp = 0; kcp < 4; kcp++) {
                const int kB = kcp * 32;
                uint32_t aH[4], aL[4];
                ldsm4(qhB + 2u * ((m0 + aRow) * HST) + kB + aColB, aH);
                ldsm4(qlB + 2u * ((m0 + aRow) * HST) + kB + aColB, aL);
                uint32_t bfh[8][2], bfl[8][2];
#pragma unroll
                for (int np = 0; np < 4; np++) {
                    uint32_t t4[4];
                    ldsm4(khB + 2u * ((np * 16 + bRow) * HST) + kB + bColB, t4);
                    bfh[2 * np][0] = t4[0]; bfh[2 * np][1] = t4[1];
                    bfh[2 * np + 1][0] = t4[2]; bfh[2 * np + 1][1] = t4[3];
                    ldsm4(klB + 2u * ((np * 16 + bRow) * HST) + kB + bColB, t4);
                    bfl[2 * np][0] = t4[0]; bfl[2 * np][1] = t4[1];
                    bfl[2 * np + 1][0] = t4[2]; bfl[2 * np + 1][1] = t4[3];
                }
#pragma unroll
                for (int nt = 0; nt < 8; nt++) {
                    mma_f16(s[nt], aL, bfh[nt]);      // Ql.Kh
                    mma_f16(s[nt], aH, bfl[nt]);      // Qh.Kl
                    mma_f16(s[nt], aH, bfh[nt]);      // Qh.Kh
                }
            }

            // ---- causal mask ----
            if (kt >= 2 * qt) {
                int q0 = qt * 128 + m0 + g, q1 = q0 + 8;
#pragma unroll
                for (int nt = 0; nt < 8; nt++) {
                    int kc0 = kt * 64 + nt * 8 + 2 * l4;
                    if (kc0 > q0) s[nt][0] = -1e30f;
                    if (kc0 + 1 > q0) s[nt][1] = -1e30f;
                    if (kc0 > q1) s[nt][2] = -1e30f;
                    if (kc0 + 1 > q1) s[nt][3] = -1e30f;
                }
            }

            // ---- online softmax (base-2) ----
#pragma unroll
            for (int r = 0; r < 2; r++) {
                float rm = -1e30f;
#pragma unroll
                for (int nt = 0; nt < 8; nt++)
                    rm = fmaxf(rm, fmaxf(s[nt][2 * r], s[nt][2 * r + 1]));
                rm = fmaxf(rm, __shfl_xor_sync(0xffffffffu, rm, 1));
                rm = fmaxf(rm, __shfl_xor_sync(0xffffffffu, rm, 2));
                float mnew = fmaxf(m_i[r], rm);
                float alpha = fast_exp2(m_i[r] - mnew);
                float rs = 0.f;
#pragma unroll
                for (int nt = 0; nt < 8; nt++) {
                    s[nt][2 * r] = fast_exp2(s[nt][2 * r] - mnew);
                    s[nt][2 * r + 1] = fast_exp2(s[nt][2 * r + 1] - mnew);
                    rs += s[nt][2 * r] + s[nt][2 * r + 1];
                }
                rs += __shfl_xor_sync(0xffffffffu, rs, 1);
                rs += __shfl_xor_sync(0xffffffffu, rs, 2);
                l_i[r] = l_i[r] * alpha + rs;
                m_i[r] = mnew;
#pragma unroll
                for (int nt = 0; nt < 8; nt++) {
                    O[nt][2 * r] *= alpha;
                    O[nt][2 * r + 1] *= alpha;
                }
            }

            // ---- stage P (single fp16 plane) ----
#pragma unroll
            for (int nt = 0; nt < 8; nt++) {
                int col = nt * 8 + 2 * l4;
                *(__half2*)&PH[(m0 + g) * HST + col] =
                    __floats2half2_rn(s[nt][0], s[nt][1]);
                *(__half2*)&PH[(m0 + g + 8) * HST + col] =
                    __floats2half2_rn(s[nt][2], s[nt][3]);
            }
            __syncwarp();   // P rows are warp-private

            // ---- O += P V (1 MMA; V row-major via ldsm.trans) ----
#pragma unroll
            for (int kcp = 0; kcp < 4; kcp++) {
                const int kB = kcp * 32;
                uint32_t pH[4];
                ldsm4(phB + 2u * ((m0 + aRow) * HST) + kB + aColB, pH);
#pragma unroll
                for (int np = 0; np < 4; np++) {
                    uint32_t tv[4];
                    ldsm4t(vhB + 2u * ((kcp * 16 + aRow) * HST + np * 16) + aColB, tv);
                    uint32_t v0[2] = {tv[0], tv[1]}, v1[2] = {tv[2], tv[3]};
                    mma_f16(O[2 * np], pH, v0);
                    mma_f16(O[2 * np + 1], pH, v1);
                }
            }
        }
        __syncthreads();   // all reads of this KV buffer done before refill
    }

    // ---- epilogue -> single fp16 plane for the output projection ----
    int b = bh >> 4, h = bh & 15;
    float inv0 = 1.0f / l_i[0], inv1 = 1.0f / l_i[1];
    int q0 = qt * 128 + m0 + g;
    size_t row0 = (size_t)(b * cT) + q0;
#pragma unroll
    for (int nt = 0; nt < 8; nt++) {
        int d = h * 64 + nt * 8 + 2 * l4;
        *(__half2*)&g_ah[row0 * cC + d] =
            __floats2half2_rn(O[nt][0] * inv0, O[nt][1] * inv0);
        *(__half2*)&g_ah[(row0 + 8) * cC + d] =
            __floats2half2_rn(O[nt][2] * inv1, O[nt][3] * inv1);
    }
}

// -------------------- launch --------------------
extern "C" void kernel_launch(void* const* d_in, const int* in_sizes, int n_in,
                              void* d_out, int out_size) {
    (void)in_sizes; (void)n_in; (void)out_size;
    const float* x = (const float*)d_in[0];
    const float* w_qkv = (const float*)d_in[1];
    const float* w_out = (const float*)d_in[2];
    float* out = (float*)d_out;

    // fused weight quantization (both tensors)
    abssum2_kernel<<<dim3(1024, 2), 256>>>(w_qkv, w_out);
    finalize2_kernel<<<2, 256>>>();
    quantize_both_kernel<<<(cNWq + cNWo) / 4 / 256, 256>>>(w_qkv, w_out);

    split_x_kernel<<<cM * cK / 4 / 256, 256>>>(x);

    // qkv projection (fp16 2-plane; V tiles 1-plane, V written as fp16 row-major)
    {
        constexpr int SM0 = 2 * 3 * APL_B;    // 61440
        cudaFuncSetAttribute(gemm_fp16_kernel<0, 2>,
                             cudaFuncAttributeMaxDynamicSharedMemorySize, SM0);
        dim3 grid(cNqkv / 128, cM / 128);
        gemm_fp16_kernel<0, 2><<<grid, 256, SM0>>>(nullptr);
    }

    // fp16 tensor-core causal flash attention (2-plane S, 1-plane PV, trans-V)
    {
        cudaFuncSetAttribute(flash_attn_f16_kernel,
                             cudaFuncAttributeMaxDynamicSharedMemorySize, ATTN_SMEM);
        dim3 grid(cT / 128, cB * cH);
        flash_attn_f16_kernel<<<grid, 256, ATTN_SMEM>>>();
    }

    // output projection (fp16 single-plane A)
    {
        constexpr int SM1 = 2 * 2 * APL_B;    // 40960
        cudaFuncSetAttribute(gemm_fp16_kernel<1, 1>,
                             cudaFuncAttributeMaxDynamicSharedMemorySize, SM1);
        dim3 grid(cC / 128, cM / 128);
        gemm_fp16_kernel<1, 1><<<grid, 256, SM1>>>(out);
    }
}